// round 5
// baseline (speedup 1.0000x reference)
#include <cuda_runtime.h>
#include <cuda_fp16.h>

#define B_      2048
#define ADIM    14
#define C_      128
#define H_      256
#define E_      182
#define NNODES  (B_*ADIM)   /* 28672 */
#define NROWS   (B_*E_)     /* 372736 */

// ---------------- device scratch (no allocs allowed) ----------------
__device__ __half g_W2h [H_*H_];        // lin2_w fp16, row-major (g, h)
__device__ __half g_Wcat[512*C_];       // [o<256: W_left rows | o>=256: W_right rows], k-contig
__device__ __half g_Xh  [NNODES*C_];    // x = g + state, fp16
__device__ float  g_Y   [NNODES*512];   // per-node [yl(256) | yr(256)]

// ---------------- mma helpers ----------------
__device__ __forceinline__ void ldsm_x4(unsigned &r0,unsigned &r1,unsigned &r2,unsigned &r3, unsigned a){
  asm volatile("ldmatrix.sync.aligned.m8n8.x4.shared.b16 {%0,%1,%2,%3},[%4];"
    :"=r"(r0),"=r"(r1),"=r"(r2),"=r"(r3):"r"(a));
}
__device__ __forceinline__ void ldsm_x2(unsigned &r0,unsigned &r1, unsigned a){
  asm volatile("ldmatrix.sync.aligned.m8n8.x2.shared.b16 {%0,%1},[%2];"
    :"=r"(r0),"=r"(r1):"r"(a));
}
__device__ __forceinline__ void mma16816(float c[4], const unsigned a[4], const unsigned b[2]){
  asm volatile("mma.sync.aligned.m16n8k16.row.col.f32.f16.f16.f32 "
    "{%0,%1,%2,%3},{%4,%5,%6,%7},{%8,%9},{%0,%1,%2,%3};"
    :"+f"(c[0]),"+f"(c[1]),"+f"(c[2]),"+f"(c[3])
    :"r"(a[0]),"r"(a[1]),"r"(a[2]),"r"(a[3]),"r"(b[0]),"r"(b[1]));
}
__device__ __forceinline__ float lky(float v){ return v > 0.f ? v : 0.01f*v; }
__device__ __forceinline__ float softplus_(float x){ return fmaxf(x,0.f) + log1pf(expf(-fabsf(x))); }

// ---------------- K0: weight conversion ----------------
__global__ void k_prep(const float* __restrict__ lin1_w, const float* __restrict__ lin2_w){
  int i = blockIdx.x*blockDim.x + threadIdx.x;   // 65536 threads
  if (i < H_*H_) g_W2h[i] = __float2half(lin2_w[i]);
  if (i < 512*C_){
    int o = i >> 7, c = i & 127;
    float v = (o < H_) ? lin1_w[o*(2*C_) + c] : lin1_w[(o-H_)*(2*C_) + C_ + c];
    g_Wcat[i] = __float2half(v);
  }
}

// ---------------- K1: s_bar -> g -> X (8 batches per block) ----------------
__global__ __launch_bounds__(256,1)
void k1_build(const float* __restrict__ state, const float* __restrict__ conv_w,
              const float* __restrict__ conv_b){
  extern __shared__ float sm1[];
  float* cw   = sm1;                 // 128 x 129
  float* sbar = cw + 128*129;        // 8 x 128
  float* gg   = sbar + 8*128;        // 8 x 128
  int tid = threadIdx.x;
  int b0  = blockIdx.x * 8;

  for (int i = tid; i < 128*128; i += 256){ int r = i>>7, c = i&127; cw[r*129+c] = conv_w[i]; }
  for (int idx = tid; idx < 8*128; idx += 256){
    int bb = idx >> 7, c = idx & 127;
    const float* sp = state + (size_t)(b0+bb)*ADIM*C_ + c;
    float s = 0.f;
    #pragma unroll
    for (int i = 0; i < ADIM; i++) s += sp[i*C_];
    sbar[idx] = s * (1.0f/14.0f);
  }
  __syncthreads();
  #pragma unroll
  for (int u = 0; u < 4; u++){
    int o = tid + u*256;             // 1024 = 8 batches * 128 outputs
    int bb = o >> 7, h = o & 127;
    const float* sb = sbar + bb*128;
    const float* w  = cw + h*129;
    float acc = 0.f;
    #pragma unroll 8
    for (int c = 0; c < 128; c++) acc += sb[c]*w[c];
    gg[o] = fmaxf(acc + conv_b[h], 0.f);
  }
  __syncthreads();
  for (int idx = tid; idx < 8*ADIM*C_; idx += 256){
    int bb = idx / (ADIM*C_); int rem = idx - bb*(ADIM*C_);
    int c  = rem & 127;
    size_t node = (size_t)(b0+bb)*ADIM + (rem >> 7);
    g_Xh[node*C_ + c] = __float2half(gg[bb*128 + c] + state[node*C_ + c]);
  }
}

// ---------------- K2: Y = X(28672x128) @ Wcat^T(128x512), fp16 mma ----------------
__global__ __launch_bounds__(256,1)
void k2_ygemm(){
  extern __shared__ __half sm2[];
  __half* As = sm2;             // 128 x 136 (pad 8)
  __half* Bs = As + 128*136;    // 128 x 136
  int tid = threadIdx.x;
  int m0 = blockIdx.x * 128, n0 = blockIdx.y * 128;

  for (int idx = tid; idx < 128*16; idx += 256){
    int r = idx >> 4, c = idx & 15;
    *(uint4*)&As[r*136 + c*8] = *(const uint4*)&g_Xh [(size_t)(m0+r)*C_ + c*8];
    *(uint4*)&Bs[r*136 + c*8] = *(const uint4*)&g_Wcat[(size_t)(n0+r)*C_ + c*8];
  }
  __syncthreads();

  int lane = tid & 31, warp = tid >> 5, wm = warp >> 2, wn = warp & 3;
  unsigned abase = (unsigned)__cvta_generic_to_shared(As);
  unsigned bbase = (unsigned)__cvta_generic_to_shared(Bs);
  float acc[4][4][4];
  #pragma unroll
  for (int i=0;i<4;i++) for (int j=0;j<4;j++) for (int q=0;q<4;q++) acc[i][j][q]=0.f;

  int rA = (lane & 7) + ((lane >> 3) & 1) * 8;
  int cA = (lane >> 4) * 8;
  int l16 = lane & 15;
  int rB = l16 & 7;
  int cB = (l16 >> 3) * 8;

  #pragma unroll
  for (int kk = 0; kk < 8; kk++){
    int k0 = kk*16;
    unsigned a[4][4], b[4][2];
    #pragma unroll
    for (int mi = 0; mi < 4; mi++){
      int row = wm*64 + mi*16 + rA;
      ldsm_x4(a[mi][0],a[mi][1],a[mi][2],a[mi][3], abase + (row*136 + k0 + cA)*2);
    }
    #pragma unroll
    for (int ni = 0; ni < 4; ni++){
      int row = wn*32 + ni*8 + rB;
      ldsm_x2(b[ni][0],b[ni][1], bbase + (row*136 + k0 + cB)*2);
    }
    #pragma unroll
    for (int mi = 0; mi < 4; mi++)
      #pragma unroll
      for (int ni = 0; ni < 4; ni++)
        mma16816(acc[mi][ni], a[mi], b[ni]);
  }
  #pragma unroll
  for (int mi = 0; mi < 4; mi++)
    #pragma unroll
    for (int ni = 0; ni < 4; ni++){
      int row = m0 + wm*64 + mi*16 + (lane >> 2);
      int col = n0 + wn*32 + ni*8 + ((lane & 3) << 1);
      *(float2*)&g_Y[(size_t)row*512 + col]     = make_float2(acc[mi][ni][0], acc[mi][ni][1]);
      *(float2*)&g_Y[(size_t)(row+8)*512 + col] = make_float2(acc[mi][ni][2], acc[mi][ni][3]);
    }
}

// ---------------- K3: fused per-batch H1 build + lin2 GEMM + heads ----------------
// 512 threads = 16 warps; warp grid 2(m) x 8(n); warp tile m48 x n32; chunk M=96.
// GEMM fragment code identical to R1 (proven); only warp-grid width and reduce width change.
__global__ __launch_bounds__(512,1)
void k3_main(const float* __restrict__ lin1_b, const float* __restrict__ lin2_b,
             const float* __restrict__ mu_w,  const float* __restrict__ mu_b,
             const float* __restrict__ sig_w, const float* __restrict__ sig_b,
             const float* __restrict__ noise, float* __restrict__ out){
  extern __shared__ float sm3[];
  float*  Ys    = sm3;                  // 14 x 512                      [0, 7168)
  float*  b1s   = Ys + ADIM*512;        // 256                           [7168, 7424)
  float*  b2f   = b1s + 256;            // 256                           [7424, 7680)
  float*  muf   = b2f + 256;            // 256                           [7680, 7936)
  float*  sgf   = muf + 256;            // 256                           [7936, 8192)
  float*  redmu = sgf + 256;            // 96 x 8                        [8192, 8960)
  float*  redsg = redmu + 96*8;         // 96 x 8                        [8960, 9728)
  float*  lp    = redsg + 96*8;         // 1 (+3 pad)                    [9728, 9732)
  __half* W2s   = (__half*)(lp + 4);    // 256 x 264 halves
  __half* H1s   = W2s + 256*264;        // 96 x 264 halves

  int tid  = threadIdx.x;
  int lane = tid & 31, warp = tid >> 5;          // 16 warps
  int warp_m = warp >> 3, warp_n = warp & 7;     // 2 x 8

  // one-time: W2 + b1 + head consts into smem
  for (int i = tid; i < 256; i += 512) b1s[i] = lin1_b[i];
  if (tid < 256){ b2f[tid] = lin2_b[tid]; muf[tid] = mu_w[tid]; sgf[tid] = sig_w[tid]; }
  for (int idx = tid; idx < 256*32; idx += 512){
    int r = idx >> 5, c = idx & 31;
    *(uint4*)&W2s[r*264 + c*8] = ((const uint4*)g_W2h)[r*32 + c];
  }
  float mub = mu_b[0], sgb = sig_b[0];
  __syncthreads();

  unsigned h1b = (unsigned)__cvta_generic_to_shared(H1s);
  unsigned w2b = (unsigned)__cvta_generic_to_shared(W2s);
  int rA = (lane & 7) + ((lane >> 3) & 1) * 8;
  int cA = (lane >> 4) * 8;
  int l16 = lane & 15;
  int rBo = l16 & 7;
  int cB  = (l16 >> 3) * 8;

  for (int b = blockIdx.x; b < B_; b += gridDim.x){
    // stage Y[b] (14 x 512 floats = 1792 float4)
    {
      const float4* ysrc = (const float4*)(g_Y + (size_t)b*ADIM*512);
      float4* ydst = (float4*)Ys;
      for (int i = tid; i < ADIM*128; i += 512) ydst[i] = ysrc[i];
      if (tid == 0) lp[0] = 0.f;
    }
    __syncthreads();

    #pragma unroll 1
    for (int chunk = 0; chunk < 2; chunk++){
      // ---- prologue: H1 rows (96 x 256) fp16, stride 264 ----
      for (int idx = tid; idx < 96*32; idx += 512){
        int m  = idx >> 5;
        int hb = (idx & 31) << 3;
        int e  = chunk*96 + m;
        union { uint4 u4; __half2 h2[4]; } P;
        if (e < E_){
          int ii = e/13; int r = e - ii*13; int jj = r + (r >= ii ? 1 : 0);
          const float* yl = Ys + ii*512 + hb;
          const float* yr = Ys + jj*512 + 256 + hb;
          const float* bp = b1s + hb;
          float v[8];
          #pragma unroll
          for (int q = 0; q < 8; q++) v[q] = lky(yl[q] + yr[q] + bp[q]);
          P.h2[0] = __floats2half2_rn(v[0], v[1]);
          P.h2[1] = __floats2half2_rn(v[2], v[3]);
          P.h2[2] = __floats2half2_rn(v[4], v[5]);
          P.h2[3] = __floats2half2_rn(v[6], v[7]);
        } else {
          P.u4 = make_uint4(0u,0u,0u,0u);
        }
        *(uint4*)&H1s[m*264 + hb] = P.u4;
      }
      __syncthreads();

      // ---- GEMM: warp tile m48 x n32, k=256 (fragments identical to R1) ----
      float acc[3][4][4];
      #pragma unroll
      for (int i=0;i<3;i++) for (int j=0;j<4;j++) for (int q=0;q<4;q++) acc[i][j][q]=0.f;

      #pragma unroll
      for (int kk = 0; kk < 16; kk++){
        int k0 = kk*16;
        unsigned a[3][4], bf[4][2];
        #pragma unroll
        for (int mi = 0; mi < 3; mi++){
          int row = warp_m*48 + mi*16 + rA;
          ldsm_x4(a[mi][0],a[mi][1],a[mi][2],a[mi][3], h1b + (row*264 + k0 + cA)*2);
        }
        #pragma unroll
        for (int ni = 0; ni < 4; ni++){
          int row = warp_n*32 + ni*8 + rBo;
          ldsm_x2(bf[ni][0],bf[ni][1], w2b + (row*264 + k0 + cB)*2);
        }
        #pragma unroll
        for (int mi = 0; mi < 3; mi++)
          #pragma unroll
          for (int ni = 0; ni < 4; ni++)
            mma16816(acc[mi][ni], a[mi], bf[ni]);
      }

      // ---- epilogue: +b2, leaky, dot with mu_w/sig_w, reduce (consts from smem) ----
      #pragma unroll
      for (int mi = 0; mi < 3; mi++){
        float pm0=0.f, ps0=0.f, pm1=0.f, ps1=0.f;
        #pragma unroll
        for (int ni = 0; ni < 4; ni++){
          int col = warp_n*32 + ni*8 + ((lane & 3) << 1);
          float2 bb = *(float2*)&b2f[col];
          float2 mm = *(float2*)&muf[col];
          float2 ss = *(float2*)&sgf[col];
          float v0 = lky(acc[mi][ni][0] + bb.x);
          float v1 = lky(acc[mi][ni][1] + bb.y);
          float v2 = lky(acc[mi][ni][2] + bb.x);
          float v3 = lky(acc[mi][ni][3] + bb.y);
          pm0 += v0*mm.x + v1*mm.y;
          ps0 += v0*ss.x + v1*ss.y;
          pm1 += v2*mm.x + v3*mm.y;
          ps1 += v2*ss.x + v3*ss.y;
        }
        pm0 += __shfl_xor_sync(0xffffffffu, pm0, 1); pm0 += __shfl_xor_sync(0xffffffffu, pm0, 2);
        ps0 += __shfl_xor_sync(0xffffffffu, ps0, 1); ps0 += __shfl_xor_sync(0xffffffffu, ps0, 2);
        pm1 += __shfl_xor_sync(0xffffffffu, pm1, 1); pm1 += __shfl_xor_sync(0xffffffffu, pm1, 2);
        ps1 += __shfl_xor_sync(0xffffffffu, ps1, 1); ps1 += __shfl_xor_sync(0xffffffffu, ps1, 2);
        if ((lane & 3) == 0){
          int row = warp_m*48 + mi*16 + (lane >> 2);
          redmu[row*8 + warp_n]     = pm0;  redsg[row*8 + warp_n]     = ps0;
          redmu[(row+8)*8 + warp_n] = pm1;  redsg[(row+8)*8 + warp_n] = ps1;
        }
      }
      __syncthreads();

      if (tid < 96){
        int e = chunk*96 + tid;
        if (e < E_){
          float mp = mub, sp = sgb;
          #pragma unroll
          for (int q = 0; q < 8; q++){ mp += redmu[tid*8 + q]; sp += redsg[tid*8 + q]; }
          float mu = softplus_(mp);
          float sd = softplus_(sp);
          float nz = noise[(size_t)b*E_ + e];
          out[(size_t)b*E_ + e] = mu + sd*nz;
          atomicAdd(lp, -0.5f*nz*nz - logf(sd));
        }
      }
      __syncthreads();
    }
    if (tid == 0) out[(size_t)NROWS + b] = lp[0] - (float)E_ * 0.91893853320467274f;
    __syncthreads();
  }
}

// ---------------- host launcher ----------------
extern "C" void kernel_launch(void* const* d_in, const int* in_sizes, int n_in,
                              void* d_out, int out_size){
  const float* state  = (const float*)d_in[0];
  const float* conv_w = (const float*)d_in[1];
  const float* conv_b = (const float*)d_in[2];
  const float* lin1_w = (const float*)d_in[3];
  const float* lin1_b = (const float*)d_in[4];
  const float* lin2_w = (const float*)d_in[5];
  const float* lin2_b = (const float*)d_in[6];
  const float* mu_w   = (const float*)d_in[7];
  const float* mu_b   = (const float*)d_in[8];
  const float* sig_w  = (const float*)d_in[9];
  const float* sig_b  = (const float*)d_in[10];
  const float* noise  = (const float*)d_in[11];
  float* out = (float*)d_out;

  const int SM1 = (128*129 + 8*128 + 8*128) * 4;                 // 74240
  const int SM2 = 2 * 128*136 * 2;                               // 69632
  // k3: 9732 floats + (256*264 + 96*264) halves = 38928 + 185856 = 224784 bytes
  const int SM3 = 9732*4 + (256*264 + 96*264)*2;

  cudaFuncSetAttribute(k1_build, cudaFuncAttributeMaxDynamicSharedMemorySize, SM1);
  cudaFuncSetAttribute(k2_ygemm, cudaFuncAttributeMaxDynamicSharedMemorySize, SM2);
  cudaFuncSetAttribute(k3_main,  cudaFuncAttributeMaxDynamicSharedMemorySize, SM3);

  k_prep<<<256, 256>>>(lin1_w, lin2_w);
  k1_build<<<256, 256, SM1>>>(state, conv_w, conv_b);
  k2_ygemm<<<dim3(224, 4), 256, SM2>>>();
  k3_main<<<152, 512, SM3>>>(lin1_b, lin2_b, mu_w, mu_b, sig_w, sig_b, noise, out);
}

// round 6
// speedup vs baseline: 1.2069x; 1.2069x over previous
#include <cuda_runtime.h>
#include <cuda_fp16.h>
#include <cstdint>

#define B_      2048
#define ADIM    14
#define C_      128
#define H_      256
#define E_      182
#define NNODES  (B_*ADIM)   /* 28672 */
#define NROWS   (B_*E_)     /* 372736 */

// ---------------- device scratch (no allocs allowed) ----------------
__device__ __align__(16) __half g_W2h [H_*H_];        // lin2_w fp16, row-major (g, h)
__device__ __align__(16) __half g_Wcat[512*C_];       // [W_left rows | W_right rows], k-contig
__device__ __align__(16) __half g_Xh  [NNODES*C_];    // x = g + state, fp16
__device__ __align__(16) __half g_Yh  [(size_t)NNODES*512]; // [yl(256,+b1) | yr(256)] fp16

// ---------------- mma helpers ----------------
__device__ __forceinline__ void ldsm_x4(unsigned &r0,unsigned &r1,unsigned &r2,unsigned &r3, unsigned a){
  asm volatile("ldmatrix.sync.aligned.m8n8.x4.shared.b16 {%0,%1,%2,%3},[%4];"
    :"=r"(r0),"=r"(r1),"=r"(r2),"=r"(r3):"r"(a));
}
__device__ __forceinline__ void ldsm_x2(unsigned &r0,unsigned &r1, unsigned a){
  asm volatile("ldmatrix.sync.aligned.m8n8.x2.shared.b16 {%0,%1},[%2];"
    :"=r"(r0),"=r"(r1):"r"(a));
}
__device__ __forceinline__ void mma16816(float c[4], const unsigned a[4], const unsigned b[2]){
  asm volatile("mma.sync.aligned.m16n8k16.row.col.f32.f16.f16.f32 "
    "{%0,%1,%2,%3},{%4,%5,%6,%7},{%8,%9},{%0,%1,%2,%3};"
    :"+f"(c[0]),"+f"(c[1]),"+f"(c[2]),"+f"(c[3])
    :"r"(a[0]),"r"(a[1]),"r"(a[2]),"r"(a[3]),"r"(b[0]),"r"(b[1]));
}
__device__ __forceinline__ void cp16(unsigned dst, const void* src){
  asm volatile("cp.async.cg.shared.global [%0], [%1], 16;" :: "r"(dst), "l"(src));
}
#define CP_COMMIT() asm volatile("cp.async.commit_group;" ::: "memory")

__device__ __forceinline__ float lky(float v){ return v > 0.f ? v : 0.01f*v; }
__device__ __forceinline__ float softplus_(float x){ return fmaxf(x,0.f) + log1pf(expf(-fabsf(x))); }

// ---------------- K0: weight conversion ----------------
__global__ void k_prep(const float* __restrict__ lin1_w, const float* __restrict__ lin2_w){
  int i = blockIdx.x*blockDim.x + threadIdx.x;   // 65536 threads
  if (i < H_*H_) g_W2h[i] = __float2half(lin2_w[i]);
  if (i < 512*C_){
    int o = i >> 7, c = i & 127;
    float v = (o < H_) ? lin1_w[o*(2*C_) + c] : lin1_w[(o-H_)*(2*C_) + C_ + c];
    g_Wcat[i] = __float2half(v);
  }
}

// ---------------- K1: s_bar -> g -> X (8 batches per block) ----------------
__global__ __launch_bounds__(256,1)
void k1_build(const float* __restrict__ state, const float* __restrict__ conv_w,
              const float* __restrict__ conv_b){
  extern __shared__ float sm1[];
  float* cw   = sm1;                 // 128 x 129
  float* sbar = cw + 128*129;        // 8 x 128
  float* gg   = sbar + 8*128;        // 8 x 128
  int tid = threadIdx.x;
  int b0  = blockIdx.x * 8;

  for (int i = tid; i < 128*128; i += 256){ int r = i>>7, c = i&127; cw[r*129+c] = conv_w[i]; }
  for (int idx = tid; idx < 8*128; idx += 256){
    int bb = idx >> 7, c = idx & 127;
    const float* sp = state + (size_t)(b0+bb)*ADIM*C_ + c;
    float s = 0.f;
    #pragma unroll
    for (int i = 0; i < ADIM; i++) s += sp[i*C_];
    sbar[idx] = s * (1.0f/14.0f);
  }
  __syncthreads();
  #pragma unroll
  for (int u = 0; u < 4; u++){
    int o = tid + u*256;             // 1024 = 8 batches * 128 outputs
    int bb = o >> 7, h = o & 127;
    const float* sb = sbar + bb*128;
    const float* w  = cw + h*129;
    float acc = 0.f;
    #pragma unroll 8
    for (int c = 0; c < 128; c++) acc += sb[c]*w[c];
    gg[o] = fmaxf(acc + conv_b[h], 0.f);
  }
  __syncthreads();
  for (int idx = tid; idx < 8*ADIM*C_; idx += 256){
    int bb = idx / (ADIM*C_); int rem = idx - bb*(ADIM*C_);
    int c  = rem & 127;
    size_t node = (size_t)(b0+bb)*ADIM + (rem >> 7);
    g_Xh[node*C_ + c] = __float2half(gg[bb*128 + c] + state[node*C_ + c]);
  }
}

// ---------------- K2: Y = X(28672x128) @ Wcat^T(128x512), fp16 out, b1 folded ----------------
__global__ __launch_bounds__(256,1)
void k2_ygemm(const float* __restrict__ lin1_b){
  extern __shared__ __half sm2[];
  __half* As = sm2;             // 128 x 136 (pad 8)
  __half* Bs = As + 128*136;    // 128 x 136
  int tid = threadIdx.x;
  int m0 = blockIdx.x * 128, n0 = blockIdx.y * 128;

  for (int idx = tid; idx < 128*16; idx += 256){
    int r = idx >> 4, c = idx & 15;
    *(uint4*)&As[r*136 + c*8] = *(const uint4*)&g_Xh [(size_t)(m0+r)*C_ + c*8];
    *(uint4*)&Bs[r*136 + c*8] = *(const uint4*)&g_Wcat[(size_t)(n0+r)*C_ + c*8];
  }
  __syncthreads();

  int lane = tid & 31, warp = tid >> 5, wm = warp >> 2, wn = warp & 3;
  unsigned abase = (unsigned)__cvta_generic_to_shared(As);
  unsigned bbase = (unsigned)__cvta_generic_to_shared(Bs);
  float acc[4][4][4];
  #pragma unroll
  for (int i=0;i<4;i++) for (int j=0;j<4;j++) for (int q=0;q<4;q++) acc[i][j][q]=0.f;

  int rA = (lane & 7) + ((lane >> 3) & 1) * 8;
  int cA = (lane >> 4) * 8;
  int l16 = lane & 15;
  int rB = l16 & 7;
  int cB = (l16 >> 3) * 8;

  #pragma unroll
  for (int kk = 0; kk < 8; kk++){
    int k0 = kk*16;
    unsigned a[4][4], b[4][2];
    #pragma unroll
    for (int mi = 0; mi < 4; mi++){
      int row = wm*64 + mi*16 + rA;
      ldsm_x4(a[mi][0],a[mi][1],a[mi][2],a[mi][3], abase + (row*136 + k0 + cA)*2);
    }
    #pragma unroll
    for (int ni = 0; ni < 4; ni++){
      int row = wn*32 + ni*8 + rB;
      ldsm_x2(b[ni][0],b[ni][1], bbase + (row*136 + k0 + cB)*2);
    }
    #pragma unroll
    for (int mi = 0; mi < 4; mi++)
      #pragma unroll
      for (int ni = 0; ni < 4; ni++)
        mma16816(acc[mi][ni], a[mi], b[ni]);
  }
  bool leftblk = (n0 < 256);
  #pragma unroll
  for (int ni = 0; ni < 4; ni++){
    int col = n0 + wn*32 + ni*8 + ((lane & 3) << 1);
    float a0 = leftblk ? __ldg(&lin1_b[col])   : 0.f;
    float a1 = leftblk ? __ldg(&lin1_b[col+1]) : 0.f;
    #pragma unroll
    for (int mi = 0; mi < 4; mi++){
      int row = m0 + wm*64 + mi*16 + (lane >> 2);
      *(__half2*)&g_Yh[(size_t)row*512 + col] =
        __floats2half2_rn(acc[mi][ni][0] + a0, acc[mi][ni][1] + a1);
      *(__half2*)&g_Yh[(size_t)(row+8)*512 + col] =
        __floats2half2_rn(acc[mi][ni][2] + a0, acc[mi][ni][3] + a1);
    }
  }
}

// ---------------- K3: persistent fused H1 build + lin2 GEMM + heads ----------------
// 512 threads = 16 warps; warp grid 2(m) x 8(n); warp tile m48 x n32 (identical to R5 core).
// Y fp16, double-buffered, cp.async prefetched. Heads overlap next build.
__global__ __launch_bounds__(512,1)
void k3_main(const float* __restrict__ lin2_b,
             const float* __restrict__ mu_w,  const float* __restrict__ mu_b,
             const float* __restrict__ sig_w, const float* __restrict__ sig_b,
             const float* __restrict__ noise, float* __restrict__ out){
  extern __shared__ float sm3[];
  float*  b2f   = sm3;                  // 256
  float*  muf   = sm3 + 256;            // 256
  float*  sgf   = sm3 + 512;            // 256
  float*  redmu = sm3 + 768;            // 96 x 8
  float*  redsg = sm3 + 1536;           // 96 x 8
  float*  lp    = sm3 + 2304;           // 1 (+pad to 2312 floats)
  __half* Ys    = (__half*)(sm3 + 2312);   // 2 x 7168 halves (double buffer)
  __half* W2s   = Ys + 14336;              // 256 x 264 halves
  __half* H1s   = W2s + 256*264;           // 96 x 264 halves

  int tid  = threadIdx.x;
  int lane = tid & 31, warp = tid >> 5;          // 16 warps
  int warp_m = warp >> 3, warp_n = warp & 7;     // 2 x 8

  // one-time: W2 + head consts into smem
  if (tid < 256){ b2f[tid] = lin2_b[tid]; muf[tid] = mu_w[tid]; sgf[tid] = sig_w[tid]; }
  for (int idx = tid; idx < 256*32; idx += 512){
    int r = idx >> 5, c = idx & 31;
    *(uint4*)&W2s[r*264 + c*8] = ((const uint4*)g_W2h)[r*32 + c];
  }
  if (tid == 0) lp[0] = 0.f;
  float mub = mu_b[0], sgb = sig_b[0];

  unsigned h1b = (unsigned)__cvta_generic_to_shared(H1s);
  unsigned w2b = (unsigned)__cvta_generic_to_shared(W2s);
  unsigned ysb = (unsigned)__cvta_generic_to_shared(Ys);
  int rA = (lane & 7) + ((lane >> 3) & 1) * 8;
  int cA = (lane >> 4) * 8;
  int l16 = lane & 15;
  int rBo = l16 & 7;
  int cB  = (l16 >> 3) * 8;

  const __half2 zero2 = __float2half2_rn(0.f);
  const __half2 s01   = __float2half2_rn(0.01f);

  int bstep = gridDim.x;
  int b = blockIdx.x;
  // prefetch first batch's Y (14 x 512 halves = 896 x 16B) into buffer 0
  if (b < B_){
    const __half* src = g_Yh + (size_t)b*ADIM*512;
    for (int g = tid; g < 896; g += 512) cp16(ysb + g*16, src + g*8);
  }
  CP_COMMIT();
  int cur = 0;

  for (; b < B_; b += bstep){
    int bn = b + bstep;
    if (bn < B_){
      unsigned dstb = ysb + (unsigned)(cur ^ 1)*14336;  // bytes
      const __half* src = g_Yh + (size_t)bn*ADIM*512;
      for (int g = tid; g < 896; g += 512) cp16(dstb + g*16, src + g*8);
      CP_COMMIT();
      asm volatile("cp.async.wait_group 1;" ::: "memory");
    } else {
      asm volatile("cp.async.wait_group 0;" ::: "memory");
    }
    __syncthreads();
    const __half* Yc = Ys + cur*7168;

    #pragma unroll 1
    for (int chunk = 0; chunk < 2; chunk++){
      // ---- build H1 chunk (96 x 256 halves, stride 264), fp16 math; b1 already in Y-left ----
      for (int idx = tid; idx < 96*32; idx += 512){
        int m  = idx >> 5;
        int c8 = idx & 31;
        int e  = chunk*96 + m;
        uint4 val;
        if (e < E_){
          int ii = e/13; int r = e - ii*13; int jj = r + (r >= ii ? 1 : 0);
          uint4 ul = *(const uint4*)&Yc[ii*512 + c8*8];
          uint4 ur = *(const uint4*)&Yc[jj*512 + 256 + c8*8];
          const __half2* l2 = (const __half2*)&ul;
          const __half2* r2 = (const __half2*)&ur;
          __half2 o[4];
          #pragma unroll
          for (int q = 0; q < 4; q++){
            __half2 s = __hadd2(l2[q], r2[q]);
            o[q] = __hadd2(__hmax2(s, zero2), __hmul2(s01, __hmin2(s, zero2)));
          }
          val = *(uint4*)o;
        } else {
          val = make_uint4(0u,0u,0u,0u);
        }
        *(uint4*)&H1s[m*264 + c8*8] = val;
      }
      __syncthreads();

      // ---- GEMM: warp tile m48 x n32, k=256 (identical to R5) ----
      float acc[3][4][4];
      #pragma unroll
      for (int i=0;i<3;i++) for (int j=0;j<4;j++) for (int q=0;q<4;q++) acc[i][j][q]=0.f;

      #pragma unroll
      for (int kk = 0; kk < 16; kk++){
        int k0 = kk*16;
        unsigned a[3][4], bf[4][2];
        #pragma unroll
        for (int mi = 0; mi < 3; mi++){
          int row = warp_m*48 + mi*16 + rA;
          ldsm_x4(a[mi][0],a[mi][1],a[mi][2],a[mi][3], h1b + (row*264 + k0 + cA)*2);
        }
        #pragma unroll
        for (int ni = 0; ni < 4; ni++){
          int row = warp_n*32 + ni*8 + rBo;
          ldsm_x2(bf[ni][0],bf[ni][1], w2b + (row*264 + k0 + cB)*2);
        }
        #pragma unroll
        for (int mi = 0; mi < 3; mi++)
          #pragma unroll
          for (int ni = 0; ni < 4; ni++)
            mma16816(acc[mi][ni], a[mi], bf[ni]);
      }

      // ---- epilogue: +b2, leaky, dot with mu_w/sig_w, reduce ----
      #pragma unroll
      for (int mi = 0; mi < 3; mi++){
        float pm0=0.f, ps0=0.f, pm1=0.f, ps1=0.f;
        #pragma unroll
        for (int ni = 0; ni < 4; ni++){
          int col = warp_n*32 + ni*8 + ((lane & 3) << 1);
          float2 bb = *(float2*)&b2f[col];
          float2 mm = *(float2*)&muf[col];
          float2 ss = *(float2*)&sgf[col];
          float v0 = lky(acc[mi][ni][0] + bb.x);
          float v1 = lky(acc[mi][ni][1] + bb.y);
          float v2 = lky(acc[mi][ni][2] + bb.x);
          float v3 = lky(acc[mi][ni][3] + bb.y);
          pm0 += v0*mm.x + v1*mm.y;
          ps0 += v0*ss.x + v1*ss.y;
          pm1 += v2*mm.x + v3*mm.y;
          ps1 += v2*ss.x + v3*ss.y;
        }
        pm0 += __shfl_xor_sync(0xffffffffu, pm0, 1); pm0 += __shfl_xor_sync(0xffffffffu, pm0, 2);
        ps0 += __shfl_xor_sync(0xffffffffu, ps0, 1); ps0 += __shfl_xor_sync(0xffffffffu, ps0, 2);
        pm1 += __shfl_xor_sync(0xffffffffu, pm1, 1); pm1 += __shfl_xor_sync(0xffffffffu, pm1, 2);
        ps1 += __shfl_xor_sync(0xffffffffu, ps1, 1); ps1 += __shfl_xor_sync(0xffffffffu, ps1, 2);
        if ((lane & 3) == 0){
          int row = warp_m*48 + mi*16 + (lane >> 2);
          redmu[row*8 + warp_n]     = pm0;  redsg[row*8 + warp_n]     = ps0;
          redmu[(row+8)*8 + warp_n] = pm1;  redsg[(row+8)*8 + warp_n] = ps1;
        }
      }
      __syncthreads();

      // ---- heads (no trailing sync: overlaps next chunk's build) ----
      if (tid < 96){
        int e = chunk*96 + tid;
        if (e < E_){
          float mp = mub, sp = sgb;
          #pragma unroll
          for (int q = 0; q < 8; q++){ mp += redmu[tid*8 + q]; sp += redsg[tid*8 + q]; }
          float mu = softplus_(mp);
          float sd = softplus_(sp);
          float nz = noise[(size_t)b*E_ + e];
          out[(size_t)b*E_ + e] = mu + sd*nz;
          atomicAdd(lp, -0.5f*nz*nz - logf(sd));
        }
      }
    }
    __syncthreads();
    if (tid == 0){
      out[(size_t)NROWS + b] = lp[0] - (float)E_ * 0.91893853320467274f;
      lp[0] = 0.f;
    }
    cur ^= 1;
  }
}

// ---------------- host launcher ----------------
extern "C" void kernel_launch(void* const* d_in, const int* in_sizes, int n_in,
                              void* d_out, int out_size){
  const float* state  = (const float*)d_in[0];
  const float* conv_w = (const float*)d_in[1];
  const float* conv_b = (const float*)d_in[2];
  const float* lin1_w = (const float*)d_in[3];
  const float* lin1_b = (const float*)d_in[4];
  const float* lin2_w = (const float*)d_in[5];
  const float* lin2_b = (const float*)d_in[6];
  const float* mu_w   = (const float*)d_in[7];
  const float* mu_b   = (const float*)d_in[8];
  const float* sig_w  = (const float*)d_in[9];
  const float* sig_b  = (const float*)d_in[10];
  const float* noise  = (const float*)d_in[11];
  float* out = (float*)d_out;

  const int SM1 = (128*129 + 8*128 + 8*128) * 4;   // 74240
  const int SM2 = 2 * 128*136 * 2;                 // 69632
  // k3: 2312 floats + (14336 + 256*264 + 96*264) halves = 9248 + 214528 = 223776 bytes
  const int SM3 = 2312*4 + (14336 + 256*264 + 96*264)*2;

  cudaFuncSetAttribute(k1_build, cudaFuncAttributeMaxDynamicSharedMemorySize, SM1);
  cudaFuncSetAttribute(k2_ygemm, cudaFuncAttributeMaxDynamicSharedMemorySize, SM2);
  cudaFuncSetAttribute(k3_main,  cudaFuncAttributeMaxDynamicSharedMemorySize, SM3);

  k_prep<<<256, 256>>>(lin1_w, lin2_w);
  k1_build<<<256, 256, SM1>>>(state, conv_w, conv_b);
  k2_ygemm<<<dim3(224, 4), 256, SM2>>>(lin1_b);
  k3_main<<<152, 512, SM3>>>(lin2_b, mu_w, mu_b, sig_w, sig_b, noise, out);
}

// round 7
// speedup vs baseline: 1.3178x; 1.0919x over previous
#include <cuda_runtime.h>
#include <cuda_fp16.h>
#include <cstdint>

#define B_      2048
#define ADIM    14
#define C_      128
#define H_      256
#define E_      182
#define NNODES  (B_*ADIM)   /* 28672 */
#define NROWS   (B_*E_)     /* 372736 */

// ---------------- device scratch (no allocs allowed) ----------------
__device__ __align__(16) __half g_W2h [H_*H_];        // lin2_w fp16, row-major (g, h)
__device__ __align__(16) __half g_Wcat[512*C_];       // [W_left rows | W_right rows], k-contig
__device__ __align__(16) __half g_Xh  [NNODES*C_];    // x = g + state, fp16
__device__ __align__(16) __half g_Yh  [(size_t)NNODES*512]; // [yl(256,+b1) | yr(256)] fp16

// ---------------- mma helpers ----------------
__device__ __forceinline__ void ldsm_x4(unsigned &r0,unsigned &r1,unsigned &r2,unsigned &r3, unsigned a){
  asm volatile("ldmatrix.sync.aligned.m8n8.x4.shared.b16 {%0,%1,%2,%3},[%4];"
    :"=r"(r0),"=r"(r1),"=r"(r2),"=r"(r3):"r"(a));
}
__device__ __forceinline__ void ldsm_x2(unsigned &r0,unsigned &r1, unsigned a){
  asm volatile("ldmatrix.sync.aligned.m8n8.x2.shared.b16 {%0,%1},[%2];"
    :"=r"(r0),"=r"(r1):"r"(a));
}
__device__ __forceinline__ void mma16816(float c[4], const unsigned a[4], const unsigned b[2]){
  asm volatile("mma.sync.aligned.m16n8k16.row.col.f32.f16.f16.f32 "
    "{%0,%1,%2,%3},{%4,%5,%6,%7},{%8,%9},{%0,%1,%2,%3};"
    :"+f"(c[0]),"+f"(c[1]),"+f"(c[2]),"+f"(c[3])
    :"r"(a[0]),"r"(a[1]),"r"(a[2]),"r"(a[3]),"r"(b[0]),"r"(b[1]));
}
__device__ __forceinline__ void cp16(unsigned dst, const void* src){
  asm volatile("cp.async.cg.shared.global [%0], [%1], 16;" :: "r"(dst), "l"(src));
}
#define CP_COMMIT() asm volatile("cp.async.commit_group;" ::: "memory")
#define CP_WAIT0()  asm volatile("cp.async.wait_group 0;" ::: "memory")

__device__ __forceinline__ float lky(float v){ return v > 0.f ? v : 0.01f*v; }
__device__ __forceinline__ float softplus_(float x){ return fmaxf(x,0.f) + log1pf(expf(-fabsf(x))); }

// ---------------- K0: weight conversion ----------------
__global__ void k_prep(const float* __restrict__ lin1_w, const float* __restrict__ lin2_w){
  int i = blockIdx.x*blockDim.x + threadIdx.x;   // 65536 threads
  if (i < H_*H_) g_W2h[i] = __float2half(lin2_w[i]);
  if (i < 512*C_){
    int o = i >> 7, c = i & 127;
    float v = (o < H_) ? lin1_w[o*(2*C_) + c] : lin1_w[(o-H_)*(2*C_) + C_ + c];
    g_Wcat[i] = __float2half(v);
  }
}

// ---------------- K1: s_bar -> g -> X (8 batches per block) ----------------
__global__ __launch_bounds__(256,1)
void k1_build(const float* __restrict__ state, const float* __restrict__ conv_w,
              const float* __restrict__ conv_b){
  extern __shared__ float sm1[];
  float* cw   = sm1;                 // 128 x 129
  float* sbar = cw + 128*129;        // 8 x 128
  float* gg   = sbar + 8*128;        // 8 x 128
  int tid = threadIdx.x;
  int b0  = blockIdx.x * 8;

  for (int i = tid; i < 128*128; i += 256){ int r = i>>7, c = i&127; cw[r*129+c] = conv_w[i]; }
  for (int idx = tid; idx < 8*128; idx += 256){
    int bb = idx >> 7, c = idx & 127;
    const float* sp = state + (size_t)(b0+bb)*ADIM*C_ + c;
    float s = 0.f;
    #pragma unroll
    for (int i = 0; i < ADIM; i++) s += sp[i*C_];
    sbar[idx] = s * (1.0f/14.0f);
  }
  __syncthreads();
  #pragma unroll
  for (int u = 0; u < 4; u++){
    int o = tid + u*256;
    int bb = o >> 7, h = o & 127;
    const float* sb = sbar + bb*128;
    const float* w  = cw + h*129;
    float acc = 0.f;
    #pragma unroll 8
    for (int c = 0; c < 128; c++) acc += sb[c]*w[c];
    gg[o] = fmaxf(acc + conv_b[h], 0.f);
  }
  __syncthreads();
  for (int idx = tid; idx < 8*ADIM*C_; idx += 256){
    int bb = idx / (ADIM*C_); int rem = idx - bb*(ADIM*C_);
    int c  = rem & 127;
    size_t node = (size_t)(b0+bb)*ADIM + (rem >> 7);
    g_Xh[node*C_ + c] = __float2half(gg[bb*128 + c] + state[node*C_ + c]);
  }
}

// ---------------- K2: Y = X @ Wcat^T, fp16 out, b1 folded ----------------
__global__ __launch_bounds__(256,1)
void k2_ygemm(const float* __restrict__ lin1_b){
  extern __shared__ __half sm2[];
  __half* As = sm2;             // 128 x 136
  __half* Bs = As + 128*136;    // 128 x 136
  int tid = threadIdx.x;
  int m0 = blockIdx.x * 128, n0 = blockIdx.y * 128;

  for (int idx = tid; idx < 128*16; idx += 256){
    int r = idx >> 4, c = idx & 15;
    *(uint4*)&As[r*136 + c*8] = *(const uint4*)&g_Xh [(size_t)(m0+r)*C_ + c*8];
    *(uint4*)&Bs[r*136 + c*8] = *(const uint4*)&g_Wcat[(size_t)(n0+r)*C_ + c*8];
  }
  __syncthreads();

  int lane = tid & 31, warp = tid >> 5, wm = warp >> 2, wn = warp & 3;
  unsigned abase = (unsigned)__cvta_generic_to_shared(As);
  unsigned bbase = (unsigned)__cvta_generic_to_shared(Bs);
  float acc[4][4][4];
  #pragma unroll
  for (int i=0;i<4;i++) for (int j=0;j<4;j++) for (int q=0;q<4;q++) acc[i][j][q]=0.f;

  int rA = (lane & 7) + ((lane >> 3) & 1) * 8;
  int cA = (lane >> 4) * 8;
  int l16 = lane & 15;
  int rB = l16 & 7;
  int cB = (l16 >> 3) * 8;

  #pragma unroll
  for (int kk = 0; kk < 8; kk++){
    int k0 = kk*16;
    unsigned a[4][4], b[4][2];
    #pragma unroll
    for (int mi = 0; mi < 4; mi++){
      int row = wm*64 + mi*16 + rA;
      ldsm_x4(a[mi][0],a[mi][1],a[mi][2],a[mi][3], abase + (row*136 + k0 + cA)*2);
    }
    #pragma unroll
    for (int ni = 0; ni < 4; ni++){
      int row = wn*32 + ni*8 + rB;
      ldsm_x2(b[ni][0],b[ni][1], bbase + (row*136 + k0 + cB)*2);
    }
    #pragma unroll
    for (int mi = 0; mi < 4; mi++)
      #pragma unroll
      for (int ni = 0; ni < 4; ni++)
        mma16816(acc[mi][ni], a[mi], b[ni]);
  }
  bool leftblk = (n0 < 256);
  #pragma unroll
  for (int ni = 0; ni < 4; ni++){
    int col = n0 + wn*32 + ni*8 + ((lane & 3) << 1);
    float a0 = leftblk ? __ldg(&lin1_b[col])   : 0.f;
    float a1 = leftblk ? __ldg(&lin1_b[col+1]) : 0.f;
    #pragma unroll
    for (int mi = 0; mi < 4; mi++){
      int row = m0 + wm*64 + mi*16 + (lane >> 2);
      *(__half2*)&g_Yh[(size_t)row*512 + col] =
        __floats2half2_rn(acc[mi][ni][0] + a0, acc[mi][ni][1] + a1);
      *(__half2*)&g_Yh[(size_t)(row+8)*512 + col] =
        __floats2half2_rn(acc[mi][ni][2] + a0, acc[mi][ni][3] + a1);
    }
  }
}

// ---------------- K3: pipelined persistent kernel ----------------
// 512 threads = 16 warps; warp grid 2(m) x 8(n); chunk M=64 (3 chunks/batch);
// H1 ping-pong so build(t+1) shares the barrier interval with GEMM(t).

__device__ __forceinline__ void build_chunk(
    int t, __half* __restrict__ H1, const __half* __restrict__ Yc, int tid)
{
  const __half2 zero2 = __float2half2_rn(0.f);
  const __half2 s01   = __float2half2_rn(0.01f);
  #pragma unroll
  for (int it = 0; it < 4; it++){
    int idx = tid + it*512;             // 64*32 entries
    int m  = idx >> 5;
    int c8 = idx & 31;
    int rg = t*64 + m;
    uint4 val;
    if (rg < E_){
      int ii = rg/13; int r = rg - ii*13; int jj = r + (r >= ii ? 1 : 0);
      uint4 ul = *(const uint4*)&Yc[ii*512 + c8*8];
      uint4 ur = *(const uint4*)&Yc[jj*512 + 256 + c8*8];
      const __half2* l2 = (const __half2*)&ul;
      const __half2* r2 = (const __half2*)&ur;
      __half2 o[4];
      #pragma unroll
      for (int q = 0; q < 4; q++){
        __half2 s = __hadd2(l2[q], r2[q]);
        o[q] = __hadd2(__hmax2(s, zero2), __hmul2(s01, __hmin2(s, zero2)));
      }
      val = *(uint4*)o;
    } else {
      val = make_uint4(0u,0u,0u,0u);
    }
    *(uint4*)&H1[m*264 + c8*8] = val;
  }
}

__device__ __forceinline__ void gemm_chunk(
    unsigned h1b, unsigned w2b, float acc[2][4][4],
    int warp_m, int warp_n, int rA, int cA, int rBo, int cB)
{
  #pragma unroll
  for (int i=0;i<2;i++) for (int j=0;j<4;j++) for (int q=0;q<4;q++) acc[i][j][q]=0.f;
  #pragma unroll
  for (int kk = 0; kk < 16; kk++){
    int k0 = kk*16;
    unsigned a[2][4], bf[4][2];
    #pragma unroll
    for (int mi = 0; mi < 2; mi++){
      int row = warp_m*32 + mi*16 + rA;
      ldsm_x4(a[mi][0],a[mi][1],a[mi][2],a[mi][3], h1b + (row*264 + k0 + cA)*2);
    }
    #pragma unroll
    for (int ni = 0; ni < 4; ni++){
      int row = warp_n*32 + ni*8 + rBo;
      ldsm_x2(bf[ni][0],bf[ni][1], w2b + (row*264 + k0 + cB)*2);
    }
    #pragma unroll
    for (int mi = 0; mi < 2; mi++)
      #pragma unroll
      for (int ni = 0; ni < 4; ni++)
        mma16816(acc[mi][ni], a[mi], bf[ni]);
  }
}

__device__ __forceinline__ void epi_red(
    float acc[2][4][4], float2* __restrict__ redt,
    const float* __restrict__ b2f, const float* __restrict__ muf, const float* __restrict__ sgf,
    int warp_m, int warp_n, int lane)
{
  #pragma unroll
  for (int mi = 0; mi < 2; mi++){
    float pm0=0.f, ps0=0.f, pm1=0.f, ps1=0.f;
    #pragma unroll
    for (int ni = 0; ni < 4; ni++){
      int col = warp_n*32 + ni*8 + ((lane & 3) << 1);
      float2 bb = *(const float2*)&b2f[col];
      float2 mm = *(const float2*)&muf[col];
      float2 ss = *(const float2*)&sgf[col];
      float v0 = lky(acc[mi][ni][0] + bb.x);
      float v1 = lky(acc[mi][ni][1] + bb.y);
      float v2 = lky(acc[mi][ni][2] + bb.x);
      float v3 = lky(acc[mi][ni][3] + bb.y);
      pm0 += v0*mm.x + v1*mm.y;
      ps0 += v0*ss.x + v1*ss.y;
      pm1 += v2*mm.x + v3*mm.y;
      ps1 += v2*ss.x + v3*ss.y;
    }
    pm0 += __shfl_xor_sync(0xffffffffu, pm0, 1); pm0 += __shfl_xor_sync(0xffffffffu, pm0, 2);
    ps0 += __shfl_xor_sync(0xffffffffu, ps0, 1); ps0 += __shfl_xor_sync(0xffffffffu, ps0, 2);
    pm1 += __shfl_xor_sync(0xffffffffu, pm1, 1); pm1 += __shfl_xor_sync(0xffffffffu, pm1, 2);
    ps1 += __shfl_xor_sync(0xffffffffu, ps1, 1); ps1 += __shfl_xor_sync(0xffffffffu, ps1, 2);
    if ((lane & 3) == 0){
      int row = warp_m*32 + mi*16 + (lane >> 2);
      redt[row*8 + warp_n]     = make_float2(pm0, ps0);
      redt[(row+8)*8 + warp_n] = make_float2(pm1, ps1);
    }
  }
}

__device__ __forceinline__ void heads_chunk(
    int t, const float2* __restrict__ redt, float* __restrict__ lp,
    const float* __restrict__ noise, float* __restrict__ out,
    int b, float mub, float sgb, int tid)
{
  if (tid < 64){
    int e = t*64 + tid;
    if (e < E_){
      float mp = mub, sp = sgb;
      #pragma unroll
      for (int q = 0; q < 8; q++){ float2 v = redt[tid*8 + q]; mp += v.x; sp += v.y; }
      float mu = softplus_(mp);
      float sd = softplus_(sp);
      float nz = noise[(size_t)b*E_ + e];
      out[(size_t)b*E_ + e] = mu + sd*nz;
      atomicAdd(lp, -0.5f*nz*nz - logf(sd));
    }
  }
}

__global__ __launch_bounds__(512,1)
void k3_main(const float* __restrict__ lin2_b,
             const float* __restrict__ mu_w,  const float* __restrict__ mu_b,
             const float* __restrict__ sig_w, const float* __restrict__ sig_b,
             const float* __restrict__ noise, float* __restrict__ out){
  extern __shared__ float sm3[];
  float*  b2f  = sm3;                       // 256
  float*  muf  = sm3 + 256;                 // 256
  float*  sgf  = sm3 + 512;                 // 256
  float2* red  = (float2*)(sm3 + 768);      // [2][64][8] float2 = 8192B (2048 floats)
  float*  lp   = sm3 + 768 + 2048;          // 4 floats
  __half* Ys   = (__half*)(sm3 + 2820);     // 7168 halves = 14336B
  __half* W2s  = Ys + 7168;                 // 256 x 264 halves
  __half* H1a  = W2s + 256*264;             // 64 x 264
  __half* H1b_ = H1a + 64*264;              // 64 x 264
  // total: 2820*4 + (7168 + 67584 + 2*16896)*2 = 11280 + 217088 = 228368 B

  int tid  = threadIdx.x;
  int lane = tid & 31, warp = tid >> 5;          // 16 warps
  int warp_m = warp >> 3, warp_n = warp & 7;     // 2 x 8

  if (tid < 256){ b2f[tid] = lin2_b[tid]; muf[tid] = mu_w[tid]; sgf[tid] = sig_w[tid]; }
  for (int idx = tid; idx < 256*32; idx += 512){
    int r = idx >> 5, c = idx & 31;
    *(uint4*)&W2s[r*264 + c*8] = ((const uint4*)g_W2h)[r*32 + c];
  }
  if (tid == 0) lp[0] = 0.f;
  float mub = mu_b[0], sgb = sig_b[0];

  unsigned h1A = (unsigned)__cvta_generic_to_shared(H1a);
  unsigned h1B = (unsigned)__cvta_generic_to_shared(H1b_);
  unsigned w2b = (unsigned)__cvta_generic_to_shared(W2s);
  unsigned ysb = (unsigned)__cvta_generic_to_shared(Ys);
  int rA = (lane & 7) + ((lane >> 3) & 1) * 8;
  int cA = (lane >> 4) * 8;
  int l16 = lane & 15;
  int rBo = l16 & 7;
  int cB  = (l16 >> 3) * 8;

  int bstep = gridDim.x;
  int b = blockIdx.x;
  if (b < B_){
    const __half* src = g_Yh + (size_t)b*ADIM*512;
    for (int g = tid; g < 896; g += 512) cp16(ysb + g*16, src + g*8);
  }
  CP_COMMIT();

  float acc[2][4][4];

  for (; b < B_; b += bstep){
    CP_WAIT0();
    __syncthreads();                       // Ys ready; H1/red free

    build_chunk(0, H1a, Ys, tid);
    __syncthreads();

    // t=0: GEMM0(H1a) | build1(H1b) | red0
    gemm_chunk(h1A, w2b, acc, warp_m, warp_n, rA, cA, rBo, cB);
    build_chunk(1, H1b_, Ys, tid);
    epi_red(acc, red, b2f, muf, sgf, warp_m, warp_n, lane);
    __syncthreads();
    heads_chunk(0, red, lp, noise, out, b, mub, sgb, tid);

    // t=1: GEMM1(H1b) | build2(H1a) | red1
    gemm_chunk(h1B, w2b, acc, warp_m, warp_n, rA, cA, rBo, cB);
    build_chunk(2, H1a, Ys, tid);
    epi_red(acc, red + 512, b2f, muf, sgf, warp_m, warp_n, lane);
    __syncthreads();
    // Ys dead (build2 done in all warps): prefetch next batch
    {
      int bn = b + bstep;
      if (bn < B_){
        const __half* src = g_Yh + (size_t)bn*ADIM*512;
        for (int g = tid; g < 896; g += 512) cp16(ysb + g*16, src + g*8);
      }
      CP_COMMIT();
    }
    heads_chunk(1, red + 512, lp, noise, out, b, mub, sgb, tid);

    // t=2: GEMM2(H1a) | red2
    gemm_chunk(h1A, w2b, acc, warp_m, warp_n, rA, cA, rBo, cB);
    epi_red(acc, red, b2f, muf, sgf, warp_m, warp_n, lane);
    __syncthreads();
    heads_chunk(2, red, lp, noise, out, b, mub, sgb, tid);
    __syncthreads();
    if (tid == 0){
      out[(size_t)NROWS + b] = lp[0] - (float)E_ * 0.91893853320467274f;
      lp[0] = 0.f;
    }
  }
}

// ---------------- host launcher ----------------
extern "C" void kernel_launch(void* const* d_in, const int* in_sizes, int n_in,
                              void* d_out, int out_size){
  const float* state  = (const float*)d_in[0];
  const float* conv_w = (const float*)d_in[1];
  const float* conv_b = (const float*)d_in[2];
  const float* lin1_w = (const float*)d_in[3];
  const float* lin1_b = (const float*)d_in[4];
  const float* lin2_w = (const float*)d_in[5];
  const float* lin2_b = (const float*)d_in[6];
  const float* mu_w   = (const float*)d_in[7];
  const float* mu_b   = (const float*)d_in[8];
  const float* sig_w  = (const float*)d_in[9];
  const float* sig_b  = (const float*)d_in[10];
  const float* noise  = (const float*)d_in[11];
  float* out = (float*)d_out;

  const int SM1 = (128*129 + 8*128 + 8*128) * 4;   // 74240
  const int SM2 = 2 * 128*136 * 2;                 // 69632
  const int SM3 = 2820*4 + (7168 + 256*264 + 2*64*264)*2;  // 228368

  cudaFuncSetAttribute(k1_build, cudaFuncAttributeMaxDynamicSharedMemorySize, SM1);
  cudaFuncSetAttribute(k2_ygemm, cudaFuncAttributeMaxDynamicSharedMemorySize, SM2);
  cudaFuncSetAttribute(k3_main,  cudaFuncAttributeMaxDynamicSharedMemorySize, SM3);

  k_prep<<<256, 256>>>(lin1_w, lin2_w);
  k1_build<<<256, 256, SM1>>>(state, conv_w, conv_b);
  k2_ygemm<<<dim3(224, 4), 256, SM2>>>(lin1_b);
  k3_main<<<152, 512, SM3>>>(lin2_b, mu_w, mu_b, sig_w, sig_b, noise, out);
}

// round 8
// speedup vs baseline: 1.7685x; 1.3420x over previous
#include <cuda_runtime.h>
#include <cuda_fp16.h>
#include <cstdint>

#define B_      2048
#define ADIM    14
#define C_      128
#define H_      256
#define E_      182
#define NNODES  (B_*ADIM)   /* 28672 */
#define NROWS   (B_*E_)     /* 372736 */
#define NPAIR   (B_/2)      /* 1024 */

// ---------------- device scratch (no allocs allowed) ----------------
__device__ __align__(16) __half g_W2h [H_*H_];        // lin2_w fp16, row-major (g, h)
__device__ __align__(16) __half g_Wcat[512*C_];       // [W_left rows | W_right rows], k-contig
__device__ __align__(16) __half g_Xh  [NNODES*C_];    // x = g + state, fp16
__device__ __align__(16) __half g_Yh  [(size_t)NNODES*512]; // [yl(256,+b1) | yr(256)] fp16
__device__ __align__(16) float2 g_part[(size_t)NPAIR*384*8]; // (pm,ps) per (pair,row,ngroup)

// ---------------- mma helpers ----------------
__device__ __forceinline__ void ldsm_x4(unsigned &r0,unsigned &r1,unsigned &r2,unsigned &r3, unsigned a){
  asm volatile("ldmatrix.sync.aligned.m8n8.x4.shared.b16 {%0,%1,%2,%3},[%4];"
    :"=r"(r0),"=r"(r1),"=r"(r2),"=r"(r3):"r"(a));
}
__device__ __forceinline__ void ldsm_x2(unsigned &r0,unsigned &r1, unsigned a){
  asm volatile("ldmatrix.sync.aligned.m8n8.x2.shared.b16 {%0,%1},[%2];"
    :"=r"(r0),"=r"(r1):"r"(a));
}
__device__ __forceinline__ void mma16816(float c[4], const unsigned a[4], const unsigned b[2]){
  asm volatile("mma.sync.aligned.m16n8k16.row.col.f32.f16.f16.f32 "
    "{%0,%1,%2,%3},{%4,%5,%6,%7},{%8,%9},{%0,%1,%2,%3};"
    :"+f"(c[0]),"+f"(c[1]),"+f"(c[2]),"+f"(c[3])
    :"r"(a[0]),"r"(a[1]),"r"(a[2]),"r"(a[3]),"r"(b[0]),"r"(b[1]));
}
__device__ __forceinline__ void cp16(unsigned dst, const void* src){
  asm volatile("cp.async.cg.shared.global [%0], [%1], 16;" :: "r"(dst), "l"(src));
}
#define CP_COMMIT() asm volatile("cp.async.commit_group;" ::: "memory")
#define CP_WAIT0()  asm volatile("cp.async.wait_group 0;" ::: "memory")

__device__ __forceinline__ float lky(float v){ return v > 0.f ? v : 0.01f*v; }
__device__ __forceinline__ float softplus_(float x){ return fmaxf(x,0.f) + log1pf(expf(-fabsf(x))); }

// ---------------- K0: weight conversion ----------------
__global__ void k_prep(const float* __restrict__ lin1_w, const float* __restrict__ lin2_w){
  int i = blockIdx.x*blockDim.x + threadIdx.x;   // 65536 threads
  if (i < H_*H_) g_W2h[i] = __float2half(lin2_w[i]);
  if (i < 512*C_){
    int o = i >> 7, c = i & 127;
    float v = (o < H_) ? lin1_w[o*(2*C_) + c] : lin1_w[(o-H_)*(2*C_) + C_ + c];
    g_Wcat[i] = __float2half(v);
  }
}

// ---------------- K1: s_bar -> g -> X (8 batches per block) ----------------
__global__ __launch_bounds__(256,1)
void k1_build(const float* __restrict__ state, const float* __restrict__ conv_w,
              const float* __restrict__ conv_b){
  extern __shared__ float sm1[];
  float* cw   = sm1;                 // 128 x 129
  float* sbar = cw + 128*129;        // 8 x 128
  float* gg   = sbar + 8*128;        // 8 x 128
  int tid = threadIdx.x;
  int b0  = blockIdx.x * 8;

  for (int i = tid; i < 128*128; i += 256){ int r = i>>7, c = i&127; cw[r*129+c] = conv_w[i]; }
  for (int idx = tid; idx < 8*128; idx += 256){
    int bb = idx >> 7, c = idx & 127;
    const float* sp = state + (size_t)(b0+bb)*ADIM*C_ + c;
    float s = 0.f;
    #pragma unroll
    for (int i = 0; i < ADIM; i++) s += sp[i*C_];
    sbar[idx] = s * (1.0f/14.0f);
  }
  __syncthreads();
  #pragma unroll
  for (int u = 0; u < 4; u++){
    int o = tid + u*256;
    int bb = o >> 7, h = o & 127;
    const float* sb = sbar + bb*128;
    const float* w  = cw + h*129;
    float acc = 0.f;
    #pragma unroll 8
    for (int c = 0; c < 128; c++) acc += sb[c]*w[c];
    gg[o] = fmaxf(acc + conv_b[h], 0.f);
  }
  __syncthreads();
  for (int idx = tid; idx < 8*ADIM*C_; idx += 256){
    int bb = idx / (ADIM*C_); int rem = idx - bb*(ADIM*C_);
    int c  = rem & 127;
    size_t node = (size_t)(b0+bb)*ADIM + (rem >> 7);
    g_Xh[node*C_ + c] = __float2half(gg[bb*128 + c] + state[node*C_ + c]);
  }
}

// ---------------- K2: Y = X @ Wcat^T, fp16 out, b1 folded ----------------
__global__ __launch_bounds__(256,1)
void k2_ygemm(const float* __restrict__ lin1_b){
  extern __shared__ __half sm2[];
  __half* As = sm2;             // 128 x 136
  __half* Bs = As + 128*136;    // 128 x 136
  int tid = threadIdx.x;
  int m0 = blockIdx.x * 128, n0 = blockIdx.y * 128;

  for (int idx = tid; idx < 128*16; idx += 256){
    int r = idx >> 4, c = idx & 15;
    *(uint4*)&As[r*136 + c*8] = *(const uint4*)&g_Xh [(size_t)(m0+r)*C_ + c*8];
    *(uint4*)&Bs[r*136 + c*8] = *(const uint4*)&g_Wcat[(size_t)(n0+r)*C_ + c*8];
  }
  __syncthreads();

  int lane = tid & 31, warp = tid >> 5, wm = warp >> 2, wn = warp & 3;
  unsigned abase = (unsigned)__cvta_generic_to_shared(As);
  unsigned bbase = (unsigned)__cvta_generic_to_shared(Bs);
  float acc[4][4][4];
  #pragma unroll
  for (int i=0;i<4;i++) for (int j=0;j<4;j++) for (int q=0;q<4;q++) acc[i][j][q]=0.f;

  int rA = (lane & 7) + ((lane >> 3) & 1) * 8;
  int cA = (lane >> 4) * 8;
  int l16 = lane & 15;
  int rB = l16 & 7;
  int cB = (l16 >> 3) * 8;

  #pragma unroll
  for (int kk = 0; kk < 8; kk++){
    int k0 = kk*16;
    unsigned a[4][4], b[4][2];
    #pragma unroll
    for (int mi = 0; mi < 4; mi++){
      int row = wm*64 + mi*16 + rA;
      ldsm_x4(a[mi][0],a[mi][1],a[mi][2],a[mi][3], abase + (row*136 + k0 + cA)*2);
    }
    #pragma unroll
    for (int ni = 0; ni < 4; ni++){
      int row = wn*32 + ni*8 + rB;
      ldsm_x2(b[ni][0],b[ni][1], bbase + (row*136 + k0 + cB)*2);
    }
    #pragma unroll
    for (int mi = 0; mi < 4; mi++)
      #pragma unroll
      for (int ni = 0; ni < 4; ni++)
        mma16816(acc[mi][ni], a[mi], b[ni]);
  }
  bool leftblk = (n0 < 256);
  #pragma unroll
  for (int ni = 0; ni < 4; ni++){
    int col = n0 + wn*32 + ni*8 + ((lane & 3) << 1);
    float a0 = leftblk ? __ldg(&lin1_b[col])   : 0.f;
    float a1 = leftblk ? __ldg(&lin1_b[col+1]) : 0.f;
    #pragma unroll
    for (int mi = 0; mi < 4; mi++){
      int row = m0 + wm*64 + mi*16 + (lane >> 2);
      *(__half2*)&g_Yh[(size_t)row*512 + col] =
        __floats2half2_rn(acc[mi][ni][0] + a0, acc[mi][ni][1] + a1);
      *(__half2*)&g_Yh[(size_t)(row+8)*512 + col] =
        __floats2half2_rn(acc[mi][ni][2] + a0, acc[mi][ni][3] + a1);
    }
  }
}

// ---------------- K3: persistent batch-pair GEMM, partials to global ----------------
// 512 threads = 16 warps; warp grid 2(m) x 8(n); warp tile m64 x n32.
// Per pair: 384 rows (2 batches padded to 192 each) in 3 chunks of M=128.
__global__ __launch_bounds__(512,1)
void k3_main(const float* __restrict__ lin2_b,
             const float* __restrict__ mu_w, const float* __restrict__ sig_w){
  extern __shared__ __half sm3[];
  __half* Ys  = sm3;                 // 2 x 14 x 512 = 14336 halves (one pair)
  __half* W2s = Ys + 14336;          // 256 x 264
  __half* H1s = W2s + 256*264;       // 128 x 264
  // total (14336 + 67584 + 33792)*2 = 231424 B

  int tid  = threadIdx.x;
  int lane = tid & 31, warp = tid >> 5;          // 16 warps
  int warp_m = warp >> 3, warp_n = warp & 7;     // 2 x 8

  // one-time: W2 into smem (stride 264)
  for (int idx = tid; idx < 256*32; idx += 512){
    int r = idx >> 5, c = idx & 31;
    *(uint4*)&W2s[r*264 + c*8] = ((const uint4*)g_W2h)[r*32 + c];
  }
  // per-thread head constants (columns fixed for CTA lifetime), fp16-packed
  __half2 b2c[4], muc[4], sgc[4];
  #pragma unroll
  for (int ni = 0; ni < 4; ni++){
    int col = warp_n*32 + ni*8 + ((lane & 3) << 1);
    b2c[ni] = __floats2half2_rn(__ldg(&lin2_b[col]), __ldg(&lin2_b[col+1]));
    muc[ni] = __floats2half2_rn(__ldg(&mu_w[col]),   __ldg(&mu_w[col+1]));
    sgc[ni] = __floats2half2_rn(__ldg(&sig_w[col]),  __ldg(&sig_w[col+1]));
  }

  unsigned h1b = (unsigned)__cvta_generic_to_shared(H1s);
  unsigned w2b = (unsigned)__cvta_generic_to_shared(W2s);
  unsigned ysb = (unsigned)__cvta_generic_to_shared(Ys);
  int rA = (lane & 7) + ((lane >> 3) & 1) * 8;
  int cA = (lane >> 4) * 8;
  int l16 = lane & 15;
  int rBo = l16 & 7;
  int cB  = (l16 >> 3) * 8;

  const __half2 zero2 = __float2half2_rn(0.f);
  const __half2 s01   = __float2half2_rn(0.01f);

  int pstep = gridDim.x;
  int pair = blockIdx.x;
  if (pair < NPAIR){
    const __half* src = g_Yh + (size_t)(pair*2)*ADIM*512;
    for (int g = tid; g < 1792; g += 512) cp16(ysb + g*16, src + g*8);
  }
  CP_COMMIT();

  for (; pair < NPAIR; pair += pstep){
    CP_WAIT0();
    __syncthreads();                 // Ys ready; H1 free (prev pair done)

    #pragma unroll 1
    for (int t = 0; t < 3; t++){
      // ---- build H1 chunk (128 x 256 halves, stride 264) ----
      #pragma unroll
      for (int it = 0; it < 8; it++){
        int idx = tid + it*512;          // 128*32
        int m  = idx >> 5;
        int c8 = idx & 31;
        int rg = t*128 + m;              // 0..383
        int bsel = (rg >= 192) ? 1 : 0;
        int e = rg - 192*bsel;
        uint4 val;
        if (e < E_){
          int ii = e/13; int r = e - ii*13; int jj = r + (r >= ii ? 1 : 0);
          uint4 ul = *(const uint4*)&Ys[(bsel*ADIM + ii)*512 + c8*8];
          uint4 ur = *(const uint4*)&Ys[(bsel*ADIM + jj)*512 + 256 + c8*8];
          const __half2* l2 = (const __half2*)&ul;
          const __half2* r2 = (const __half2*)&ur;
          __half2 o[4];
          #pragma unroll
          for (int q = 0; q < 4; q++){
            __half2 s = __hadd2(l2[q], r2[q]);
            o[q] = __hadd2(__hmax2(s, zero2), __hmul2(s01, __hmin2(s, zero2)));
          }
          val = *(uint4*)o;
        } else {
          val = make_uint4(0u,0u,0u,0u);
        }
        *(uint4*)&H1s[m*264 + c8*8] = val;
      }
      __syncthreads();

      // after last build, Ys is dead: prefetch next pair (overlaps gemm2)
      if (t == 2){
        int pn = pair + pstep;
        if (pn < NPAIR){
          const __half* src = g_Yh + (size_t)(pn*2)*ADIM*512;
          for (int g = tid; g < 1792; g += 512) cp16(ysb + g*16, src + g*8);
        }
        CP_COMMIT();
      }

      // ---- GEMM: warp tile m64 x n32, k=256 ----
      float acc[4][4][4];
      #pragma unroll
      for (int i=0;i<4;i++) for (int j=0;j<4;j++) for (int q=0;q<4;q++) acc[i][j][q]=0.f;

      #pragma unroll
      for (int kk = 0; kk < 16; kk++){
        int k0 = kk*16;
        unsigned a[4][4], bf[4][2];
        #pragma unroll
        for (int mi = 0; mi < 4; mi++){
          int row = warp_m*64 + mi*16 + rA;
          ldsm_x4(a[mi][0],a[mi][1],a[mi][2],a[mi][3], h1b + (row*264 + k0 + cA)*2);
        }
        #pragma unroll
        for (int ni = 0; ni < 4; ni++){
          int row = warp_n*32 + ni*8 + rBo;
          ldsm_x2(bf[ni][0],bf[ni][1], w2b + (row*264 + k0 + cB)*2);
        }
        #pragma unroll
        for (int mi = 0; mi < 4; mi++)
          #pragma unroll
          for (int ni = 0; ni < 4; ni++)
            mma16816(acc[mi][ni], a[mi], bf[ni]);
      }

      // ---- epilogue: +b2, leaky, mu/sig dots, shfl-reduce, STG partials ----
      float2* pbase = g_part + ((size_t)pair*384 + t*128)*8 + warp_n;
      #pragma unroll
      for (int mi = 0; mi < 4; mi++){
        float pm0=0.f, ps0=0.f, pm1=0.f, ps1=0.f;
        #pragma unroll
        for (int ni = 0; ni < 4; ni++){
          float2 bb = __half22float2(b2c[ni]);
          float2 mm = __half22float2(muc[ni]);
          float2 ss = __half22float2(sgc[ni]);
          float v0 = lky(acc[mi][ni][0] + bb.x);
          float v1 = lky(acc[mi][ni][1] + bb.y);
          float v2 = lky(acc[mi][ni][2] + bb.x);
          float v3 = lky(acc[mi][ni][3] + bb.y);
          pm0 += v0*mm.x + v1*mm.y;
          ps0 += v0*ss.x + v1*ss.y;
          pm1 += v2*mm.x + v3*mm.y;
          ps1 += v2*ss.x + v3*ss.y;
        }
        pm0 += __shfl_xor_sync(0xffffffffu, pm0, 1); pm0 += __shfl_xor_sync(0xffffffffu, pm0, 2);
        ps0 += __shfl_xor_sync(0xffffffffu, ps0, 1); ps0 += __shfl_xor_sync(0xffffffffu, ps0, 2);
        pm1 += __shfl_xor_sync(0xffffffffu, pm1, 1); pm1 += __shfl_xor_sync(0xffffffffu, pm1, 2);
        ps1 += __shfl_xor_sync(0xffffffffu, ps1, 1); ps1 += __shfl_xor_sync(0xffffffffu, ps1, 2);
        if ((lane & 3) == 0){
          int row = warp_m*64 + mi*16 + (lane >> 2);
          pbase[(size_t)row*8]     = make_float2(pm0, ps0);
          pbase[(size_t)(row+8)*8] = make_float2(pm1, ps1);
        }
      }
      __syncthreads();               // H1 (and at t==2: nothing else) reuse guard
    }
  }
}

// ---------------- K4: heads + log-prob from partials ----------------
__global__ __launch_bounds__(192,1)
void k4_heads(const float* __restrict__ mu_b, const float* __restrict__ sig_b,
              const float* __restrict__ noise, float* __restrict__ out){
  __shared__ float wsum[6];
  int b = blockIdx.x;                 // 0..2047
  int tid = threadIdx.x;              // 0..191
  int pair = b >> 1, half = b & 1;
  const float2* src = g_part + ((size_t)pair*384 + half*192 + tid)*8;
  float mp = mu_b[0], sp = sig_b[0];
  #pragma unroll
  for (int q = 0; q < 8; q++){ float2 v = src[q]; mp += v.x; sp += v.y; }
  float c = 0.f;
  if (tid < E_){
    float mu = softplus_(mp);
    float sd = softplus_(sp);
    float nz = noise[(size_t)b*E_ + tid];
    out[(size_t)b*E_ + tid] = mu + sd*nz;
    c = -0.5f*nz*nz - logf(sd);
  }
  c += __shfl_xor_sync(0xffffffffu, c, 1);
  c += __shfl_xor_sync(0xffffffffu, c, 2);
  c += __shfl_xor_sync(0xffffffffu, c, 4);
  c += __shfl_xor_sync(0xffffffffu, c, 8);
  c += __shfl_xor_sync(0xffffffffu, c, 16);
  if ((tid & 31) == 0) wsum[tid >> 5] = c;
  __syncthreads();
  if (tid == 0){
    float s = wsum[0] + wsum[1] + wsum[2] + wsum[3] + wsum[4] + wsum[5];
    out[(size_t)NROWS + b] = s - (float)E_ * 0.91893853320467274f;
  }
}

// ---------------- host launcher ----------------
extern "C" void kernel_launch(void* const* d_in, const int* in_sizes, int n_in,
                              void* d_out, int out_size){
  const float* state  = (const float*)d_in[0];
  const float* conv_w = (const float*)d_in[1];
  const float* conv_b = (const float*)d_in[2];
  const float* lin1_w = (const float*)d_in[3];
  const float* lin1_b = (const float*)d_in[4];
  const float* lin2_w = (const float*)d_in[5];
  const float* lin2_b = (const float*)d_in[6];
  const float* mu_w   = (const float*)d_in[7];
  const float* mu_b   = (const float*)d_in[8];
  const float* sig_w  = (const float*)d_in[9];
  const float* sig_b  = (const float*)d_in[10];
  const float* noise  = (const float*)d_in[11];
  float* out = (float*)d_out;

  const int SM1 = (128*129 + 8*128 + 8*128) * 4;       // 74240
  const int SM2 = 2 * 128*136 * 2;                     // 69632
  const int SM3 = (14336 + 256*264 + 128*264) * 2;     // 231424

  cudaFuncSetAttribute(k1_build, cudaFuncAttributeMaxDynamicSharedMemorySize, SM1);
  cudaFuncSetAttribute(k2_ygemm, cudaFuncAttributeMaxDynamicSharedMemorySize, SM2);
  cudaFuncSetAttribute(k3_main,  cudaFuncAttributeMaxDynamicSharedMemorySize, SM3);

  k_prep<<<256, 256>>>(lin1_w, lin2_w);
  k1_build<<<256, 256, SM1>>>(state, conv_w, conv_b);
  k2_ygemm<<<dim3(224, 4), 256, SM2>>>(lin1_b);
  k3_main<<<152, 512, SM3>>>(lin2_b, mu_w, sig_w);
  k4_heads<<<B_, 192>>>(mu_b, sig_b, noise, out);
}

// round 9
// speedup vs baseline: 1.8029x; 1.0195x over previous
#include <cuda_runtime.h>
#include <cuda_fp16.h>
#include <cstdint>

#define B_      2048
#define ADIM    14
#define C_      128
#define H_      256
#define E_      182
#define NNODES  (B_*ADIM)   /* 28672 */
#define NROWS   (B_*E_)     /* 372736 */
#define NPAIR   (B_/2)      /* 1024 */

// ---------------- device scratch (no allocs allowed) ----------------
__device__ __align__(16) __half g_W2h [H_*H_];        // lin2_w fp16, row-major (g, h)
__device__ __align__(16) __half g_Wcat[512*C_];       // [W_left rows | W_right rows], k-contig
__device__ __align__(16) __half g_Xh  [NNODES*C_];    // x = g + state, fp16
__device__ __align__(16) __half g_Yh  [(size_t)NNODES*512]; // [yl(256,+b1) | yr(256)] fp16
__device__ __align__(16) float2 g_part[(size_t)NPAIR*384*8]; // (pm,ps) per (pair,row,ngroup)

// ---------------- mma helpers ----------------
__device__ __forceinline__ void ldsm_x4(unsigned &r0,unsigned &r1,unsigned &r2,unsigned &r3, unsigned a){
  asm volatile("ldmatrix.sync.aligned.m8n8.x4.shared.b16 {%0,%1,%2,%3},[%4];"
    :"=r"(r0),"=r"(r1),"=r"(r2),"=r"(r3):"r"(a));
}
__device__ __forceinline__ void ldsm_x2(unsigned &r0,unsigned &r1, unsigned a){
  asm volatile("ldmatrix.sync.aligned.m8n8.x2.shared.b16 {%0,%1},[%2];"
    :"=r"(r0),"=r"(r1):"r"(a));
}
__device__ __forceinline__ void mma16816(float c[4], const unsigned a[4], const unsigned b[2]){
  asm volatile("mma.sync.aligned.m16n8k16.row.col.f32.f16.f16.f32 "
    "{%0,%1,%2,%3},{%4,%5,%6,%7},{%8,%9},{%0,%1,%2,%3};"
    :"+f"(c[0]),"+f"(c[1]),"+f"(c[2]),"+f"(c[3])
    :"r"(a[0]),"r"(a[1]),"r"(a[2]),"r"(a[3]),"r"(b[0]),"r"(b[1]));
}
__device__ __forceinline__ void cp16(unsigned dst, const void* src){
  asm volatile("cp.async.cg.shared.global [%0], [%1], 16;" :: "r"(dst), "l"(src));
}
#define CP_COMMIT() asm volatile("cp.async.commit_group;" ::: "memory")
#define CP_WAIT0()  asm volatile("cp.async.wait_group 0;" ::: "memory")

__device__ __forceinline__ float lky(float v){ return v > 0.f ? v : 0.01f*v; }
__device__ __forceinline__ float softplus_(float x){ return fmaxf(x,0.f) + log1pf(expf(-fabsf(x))); }

// ---------------- K0: weight conversion ----------------
__global__ void k_prep(const float* __restrict__ lin1_w, const float* __restrict__ lin2_w){
  int i = blockIdx.x*blockDim.x + threadIdx.x;   // 65536 threads
  if (i < H_*H_) g_W2h[i] = __float2half(lin2_w[i]);
  if (i < 512*C_){
    int o = i >> 7, c = i & 127;
    float v = (o < H_) ? lin1_w[o*(2*C_) + c] : lin1_w[(o-H_)*(2*C_) + C_ + c];
    g_Wcat[i] = __float2half(v);
  }
}

// ---------------- K1: s_bar -> g -> X (8 batches per block) ----------------
__global__ __launch_bounds__(256,1)
void k1_build(const float* __restrict__ state, const float* __restrict__ conv_w,
              const float* __restrict__ conv_b){
  extern __shared__ float sm1[];
  float* cw   = sm1;                 // 128 x 129
  float* sbar = cw + 128*129;        // 8 x 128
  float* gg   = sbar + 8*128;        // 8 x 128
  int tid = threadIdx.x;
  int b0  = blockIdx.x * 8;

  for (int i = tid; i < 128*128; i += 256){ int r = i>>7, c = i&127; cw[r*129+c] = conv_w[i]; }
  for (int idx = tid; idx < 8*128; idx += 256){
    int bb = idx >> 7, c = idx & 127;
    const float* sp = state + (size_t)(b0+bb)*ADIM*C_ + c;
    float s = 0.f;
    #pragma unroll
    for (int i = 0; i < ADIM; i++) s += sp[i*C_];
    sbar[idx] = s * (1.0f/14.0f);
  }
  __syncthreads();
  #pragma unroll
  for (int u = 0; u < 4; u++){
    int o = tid + u*256;
    int bb = o >> 7, h = o & 127;
    const float* sb = sbar + bb*128;
    const float* w  = cw + h*129;
    float acc = 0.f;
    #pragma unroll 8
    for (int c = 0; c < 128; c++) acc += sb[c]*w[c];
    gg[o] = fmaxf(acc + conv_b[h], 0.f);
  }
  __syncthreads();
  for (int idx = tid; idx < 8*ADIM*C_; idx += 256){
    int bb = idx / (ADIM*C_); int rem = idx - bb*(ADIM*C_);
    int c  = rem & 127;
    size_t node = (size_t)(b0+bb)*ADIM + (rem >> 7);
    g_Xh[node*C_ + c] = __float2half(gg[bb*128 + c] + state[node*C_ + c]);
  }
}

// ---------------- K2: Y = X @ Wcat^T, fp16 out, b1 folded ----------------
__global__ __launch_bounds__(256,1)
void k2_ygemm(const float* __restrict__ lin1_b){
  extern __shared__ __half sm2[];
  __half* As = sm2;             // 128 x 136
  __half* Bs = As + 128*136;    // 128 x 136
  int tid = threadIdx.x;
  int m0 = blockIdx.x * 128, n0 = blockIdx.y * 128;

  for (int idx = tid; idx < 128*16; idx += 256){
    int r = idx >> 4, c = idx & 15;
    *(uint4*)&As[r*136 + c*8] = *(const uint4*)&g_Xh [(size_t)(m0+r)*C_ + c*8];
    *(uint4*)&Bs[r*136 + c*8] = *(const uint4*)&g_Wcat[(size_t)(n0+r)*C_ + c*8];
  }
  __syncthreads();

  int lane = tid & 31, warp = tid >> 5, wm = warp >> 2, wn = warp & 3;
  unsigned abase = (unsigned)__cvta_generic_to_shared(As);
  unsigned bbase = (unsigned)__cvta_generic_to_shared(Bs);
  float acc[4][4][4];
  #pragma unroll
  for (int i=0;i<4;i++) for (int j=0;j<4;j++) for (int q=0;q<4;q++) acc[i][j][q]=0.f;

  int rA = (lane & 7) + ((lane >> 3) & 1) * 8;
  int cA = (lane >> 4) * 8;
  int l16 = lane & 15;
  int rB = l16 & 7;
  int cB = (l16 >> 3) * 8;

  #pragma unroll
  for (int kk = 0; kk < 8; kk++){
    int k0 = kk*16;
    unsigned a[4][4], b[4][2];
    #pragma unroll
    for (int mi = 0; mi < 4; mi++){
      int row = wm*64 + mi*16 + rA;
      ldsm_x4(a[mi][0],a[mi][1],a[mi][2],a[mi][3], abase + (row*136 + k0 + cA)*2);
    }
    #pragma unroll
    for (int ni = 0; ni < 4; ni++){
      int row = wn*32 + ni*8 + rB;
      ldsm_x2(b[ni][0],b[ni][1], bbase + (row*136 + k0 + cB)*2);
    }
    #pragma unroll
    for (int mi = 0; mi < 4; mi++)
      #pragma unroll
      for (int ni = 0; ni < 4; ni++)
        mma16816(acc[mi][ni], a[mi], b[ni]);
  }
  bool leftblk = (n0 < 256);
  #pragma unroll
  for (int ni = 0; ni < 4; ni++){
    int col = n0 + wn*32 + ni*8 + ((lane & 3) << 1);
    float a0 = leftblk ? __ldg(&lin1_b[col])   : 0.f;
    float a1 = leftblk ? __ldg(&lin1_b[col+1]) : 0.f;
    #pragma unroll
    for (int mi = 0; mi < 4; mi++){
      int row = m0 + wm*64 + mi*16 + (lane >> 2);
      *(__half2*)&g_Yh[(size_t)row*512 + col] =
        __floats2half2_rn(acc[mi][ni][0] + a0, acc[mi][ni][1] + a1);
      *(__half2*)&g_Yh[(size_t)(row+8)*512 + col] =
        __floats2half2_rn(acc[mi][ni][2] + a0, acc[mi][ni][3] + a1);
    }
  }
}

// ---------------- K3: warp-specialized producer/consumer GEMM ----------------
// 384 threads: warps 0-7 = GEMM (warp tile m64 x n32, grid 1m x 8n, chunk M=64),
// warps 8-11 = builders (H1 double-buffered) + Ys prefetch.
__global__ __launch_bounds__(384,1)
void k3_main(const float* __restrict__ lin2_b,
             const float* __restrict__ mu_w, const float* __restrict__ sig_w){
  extern __shared__ __half sm3[];
  __half* Ys  = sm3;                 // 2 x 14 x 512 = 14336 halves (one pair)
  __half* W2s = Ys + 14336;          // 256 x 264 = 67584
  __half* H1a = W2s + 67584;         // 64 x 264 = 16896
  __half* H1b = H1a + 16896;         // 64 x 264 = 16896
  // total (14336 + 67584 + 2*16896)*2 = 231424 B

  int tid  = threadIdx.x;
  int lane = tid & 31, warp = tid >> 5;          // 12 warps
  bool isg = (warp < 8);
  int warp_n = warp & 7;

  // one-time: W2 into smem (stride 264)
  for (int idx = tid; idx < 256*32; idx += 384){
    int r = idx >> 5, c = idx & 31;
    *(uint4*)&W2s[r*264 + c*8] = ((const uint4*)g_W2h)[r*32 + c];
  }
  // per-thread head constants (GEMM warps; columns fixed for CTA lifetime)
  __half2 b2c[4], muc[4], sgc[4];
  if (isg){
    #pragma unroll
    for (int ni = 0; ni < 4; ni++){
      int col = warp_n*32 + ni*8 + ((lane & 3) << 1);
      b2c[ni] = __floats2half2_rn(__ldg(&lin2_b[col]), __ldg(&lin2_b[col+1]));
      muc[ni] = __floats2half2_rn(__ldg(&mu_w[col]),   __ldg(&mu_w[col+1]));
      sgc[ni] = __floats2half2_rn(__ldg(&sig_w[col]),  __ldg(&sig_w[col+1]));
    }
  }

  unsigned h1bs[2] = { (unsigned)__cvta_generic_to_shared(H1a),
                       (unsigned)__cvta_generic_to_shared(H1b) };
  unsigned w2b = (unsigned)__cvta_generic_to_shared(W2s);
  unsigned ysb = (unsigned)__cvta_generic_to_shared(Ys);
  int rA = (lane & 7) + ((lane >> 3) & 1) * 8;
  int cA = (lane >> 4) * 8;
  int l16 = lane & 15;
  int rBo = l16 & 7;
  int cB  = (l16 >> 3) * 8;

  const __half2 zero2 = __float2half2_rn(0.f);
  const __half2 s01   = __float2half2_rn(0.01f);

  int pstep = gridDim.x;
  int pair = blockIdx.x;
  // initial Ys prefetch: all threads participate
  if (pair < NPAIR){
    const __half* src = g_Yh + (size_t)(pair*2)*ADIM*512;
    for (int g = tid; g < 1792; g += 384) cp16(ysb + g*16, src + g*8);
  }
  CP_COMMIT();

  int bt = tid & 127;   // builder-local index (valid when !isg)

  for (; pair < NPAIR; pair += pstep){
    CP_WAIT0();
    __syncthreads();                 // Ys ready; both H1 buffers free

    // builders: chunk 0 into H1a
    if (!isg){
      #pragma unroll
      for (int it = 0; it < 16; it++){
        int idx = bt + it*128;       // 64*32 entries
        int m  = idx >> 5;
        int c8 = idx & 31;
        int e  = m;                  // rg = 0*64 + m; bsel=0
        uint4 val;
        {
          int ii = e/13; int r = e - ii*13; int jj = r + (r >= ii ? 1 : 0);
          uint4 ul = *(const uint4*)&Ys[ii*512 + c8*8];
          uint4 ur = *(const uint4*)&Ys[jj*512 + 256 + c8*8];
          const __half2* l2 = (const __half2*)&ul;
          const __half2* r2 = (const __half2*)&ur;
          __half2 o[4];
          #pragma unroll
          for (int q = 0; q < 4; q++){
            __half2 s = __hadd2(l2[q], r2[q]);
            o[q] = __hadd2(__hmax2(s, zero2), __hmul2(s01, __hmin2(s, zero2)));
          }
          val = *(uint4*)o;
        }
        *(uint4*)&H1a[m*264 + c8*8] = val;
      }
    }
    __syncthreads();

    #pragma unroll 1
    for (int t = 0; t < 6; t++){
      if (isg){
        // ---- GEMM chunk t on H1[t&1]: warp tile m64 x n32, k=256 ----
        unsigned h1b = h1bs[t & 1];
        float acc[4][4][4];
        #pragma unroll
        for (int i=0;i<4;i++) for (int j=0;j<4;j++) for (int q=0;q<4;q++) acc[i][j][q]=0.f;

        #pragma unroll
        for (int kk = 0; kk < 16; kk++){
          int k0 = kk*16;
          unsigned a[4][4], bf[4][2];
          #pragma unroll
          for (int mi = 0; mi < 4; mi++){
            int row = mi*16 + rA;
            ldsm_x4(a[mi][0],a[mi][1],a[mi][2],a[mi][3], h1b + (row*264 + k0 + cA)*2);
          }
          #pragma unroll
          for (int ni = 0; ni < 4; ni++){
            int row = warp_n*32 + ni*8 + rBo;
            ldsm_x2(bf[ni][0],bf[ni][1], w2b + (row*264 + k0 + cB)*2);
          }
          #pragma unroll
          for (int mi = 0; mi < 4; mi++)
            #pragma unroll
            for (int ni = 0; ni < 4; ni++)
              mma16816(acc[mi][ni], a[mi], bf[ni]);
        }

        // ---- epilogue: +b2, leaky, mu/sig dots, shfl-reduce, STG partials ----
        float2* pbase = g_part + ((size_t)pair*384 + t*64)*8 + warp_n;
        #pragma unroll
        for (int mi = 0; mi < 4; mi++){
          float pm0=0.f, ps0=0.f, pm1=0.f, ps1=0.f;
          #pragma unroll
          for (int ni = 0; ni < 4; ni++){
            float2 bb = __half22float2(b2c[ni]);
            float2 mm = __half22float2(muc[ni]);
            float2 ss = __half22float2(sgc[ni]);
            float v0 = lky(acc[mi][ni][0] + bb.x);
            float v1 = lky(acc[mi][ni][1] + bb.y);
            float v2 = lky(acc[mi][ni][2] + bb.x);
            float v3 = lky(acc[mi][ni][3] + bb.y);
            pm0 += v0*mm.x + v1*mm.y;
            ps0 += v0*ss.x + v1*ss.y;
            pm1 += v2*mm.x + v3*mm.y;
            ps1 += v2*ss.x + v3*ss.y;
          }
          pm0 += __shfl_xor_sync(0xffffffffu, pm0, 1); pm0 += __shfl_xor_sync(0xffffffffu, pm0, 2);
          ps0 += __shfl_xor_sync(0xffffffffu, ps0, 1); ps0 += __shfl_xor_sync(0xffffffffu, ps0, 2);
          pm1 += __shfl_xor_sync(0xffffffffu, pm1, 1); pm1 += __shfl_xor_sync(0xffffffffu, pm1, 2);
          ps1 += __shfl_xor_sync(0xffffffffu, ps1, 1); ps1 += __shfl_xor_sync(0xffffffffu, ps1, 2);
          if ((lane & 3) == 0){
            int row = mi*16 + (lane >> 2);
            pbase[(size_t)row*8]     = make_float2(pm0, ps0);
            pbase[(size_t)(row+8)*8] = make_float2(pm1, ps1);
          }
        }
      } else {
        if (t < 5){
          // ---- build chunk t+1 into H1[(t+1)&1] ----
          __half* H1d = (((t+1) & 1) ? H1b : H1a);
          int tc = t + 1;
          #pragma unroll
          for (int it = 0; it < 16; it++){
            int idx = bt + it*128;
            int m  = idx >> 5;
            int c8 = idx & 31;
            int rg = tc*64 + m;            // 64..383
            int bsel = (rg >= 192) ? 1 : 0;
            int e = rg - 192*bsel;
            uint4 val;
            if (e < E_){
              int ii = e/13; int r = e - ii*13; int jj = r + (r >= ii ? 1 : 0);
              uint4 ul = *(const uint4*)&Ys[(bsel*ADIM + ii)*512 + c8*8];
              uint4 ur = *(const uint4*)&Ys[(bsel*ADIM + jj)*512 + 256 + c8*8];
              const __half2* l2 = (const __half2*)&ul;
              const __half2* r2 = (const __half2*)&ur;
              __half2 o[4];
              #pragma unroll
              for (int q = 0; q < 4; q++){
                __half2 s = __hadd2(l2[q], r2[q]);
                o[q] = __hadd2(__hmax2(s, zero2), __hmul2(s01, __hmin2(s, zero2)));
              }
              val = *(uint4*)o;
            } else {
              val = make_uint4(0u,0u,0u,0u);
            }
            *(uint4*)&H1d[m*264 + c8*8] = val;
          }
        } else {
          // ---- t==5: Ys dead, prefetch next pair ----
          int pn = pair + pstep;
          if (pn < NPAIR){
            const __half* src = g_Yh + (size_t)(pn*2)*ADIM*512;
            for (int g = bt; g < 1792; g += 128) cp16(ysb + g*16, src + g*8);
          }
          CP_COMMIT();
        }
      }
      __syncthreads();
    }
  }
}

// ---------------- K4: heads + log-prob from partials ----------------
__global__ __launch_bounds__(192,1)
void k4_heads(const float* __restrict__ mu_b, const float* __restrict__ sig_b,
              const float* __restrict__ noise, float* __restrict__ out){
  __shared__ float wsum[6];
  int b = blockIdx.x;                 // 0..2047
  int tid = threadIdx.x;              // 0..191
  int pair = b >> 1, half = b & 1;
  const float2* src = g_part + ((size_t)pair*384 + half*192 + tid)*8;
  float mp = mu_b[0], sp = sig_b[0];
  #pragma unroll
  for (int q = 0; q < 8; q++){ float2 v = src[q]; mp += v.x; sp += v.y; }
  float c = 0.f;
  if (tid < E_){
    float mu = softplus_(mp);
    float sd = softplus_(sp);
    float nz = noise[(size_t)b*E_ + tid];
    out[(size_t)b*E_ + tid] = mu + sd*nz;
    c = -0.5f*nz*nz - logf(sd);
  }
  c += __shfl_xor_sync(0xffffffffu, c, 1);
  c += __shfl_xor_sync(0xffffffffu, c, 2);
  c += __shfl_xor_sync(0xffffffffu, c, 4);
  c += __shfl_xor_sync(0xffffffffu, c, 8);
  c += __shfl_xor_sync(0xffffffffu, c, 16);
  if ((tid & 31) == 0) wsum[tid >> 5] = c;
  __syncthreads();
  if (tid == 0){
    float s = wsum[0] + wsum[1] + wsum[2] + wsum[3] + wsum[4] + wsum[5];
    out[(size_t)NROWS + b] = s - (float)E_ * 0.91893853320467274f;
  }
}

// ---------------- host launcher ----------------
extern "C" void kernel_launch(void* const* d_in, const int* in_sizes, int n_in,
                              void* d_out, int out_size){
  const float* state  = (const float*)d_in[0];
  const float* conv_w = (const float*)d_in[1];
  const float* conv_b = (const float*)d_in[2];
  const float* lin1_w = (const float*)d_in[3];
  const float* lin1_b = (const float*)d_in[4];
  const float* lin2_w = (const float*)d_in[5];
  const float* lin2_b = (const float*)d_in[6];
  const float* mu_w   = (const float*)d_in[7];
  const float* mu_b   = (const float*)d_in[8];
  const float* sig_w  = (const float*)d_in[9];
  const float* sig_b  = (const float*)d_in[10];
  const float* noise  = (const float*)d_in[11];
  float* out = (float*)d_out;

  const int SM1 = (128*129 + 8*128 + 8*128) * 4;           // 74240
  const int SM2 = 2 * 128*136 * 2;                         // 69632
  const int SM3 = (14336 + 256*264 + 2*64*264) * 2;        // 231424

  cudaFuncSetAttribute(k1_build, cudaFuncAttributeMaxDynamicSharedMemorySize, SM1);
  cudaFuncSetAttribute(k2_ygemm, cudaFuncAttributeMaxDynamicSharedMemorySize, SM2);
  cudaFuncSetAttribute(k3_main,  cudaFuncAttributeMaxDynamicSharedMemorySize, SM3);

  k_prep<<<256, 256>>>(lin1_w, lin2_w);
  k1_build<<<256, 256, SM1>>>(state, conv_w, conv_b);
  k2_ygemm<<<dim3(224, 4), 256, SM2>>>(lin1_b);
  k3_main<<<152, 384, SM3>>>(lin2_b, mu_w, sig_w);
  k4_heads<<<B_, 192>>>(mu_b, sig_b, noise, out);
}

// round 10
// speedup vs baseline: 1.8405x; 1.0208x over previous
#include <cuda_runtime.h>
#include <cuda_fp16.h>
#include <cstdint>

#define B_      2048
#define ADIM    14
#define C_      128
#define H_      256
#define E_      182
#define NNODES  (B_*ADIM)   /* 28672 */
#define NROWS   (B_*E_)     /* 372736 */
#define NPAIR   (B_/2)      /* 1024 */

// ---------------- device scratch (no allocs allowed) ----------------
__device__ __align__(16) __half g_W2h [H_*H_];        // lin2_w fp16, row-major (g, h)
__device__ __align__(16) __half g_Wcat[512*C_];       // [W_left rows | W_right rows], k-contig
__device__ __align__(16) __half g_Xh  [NNODES*C_];    // x = g + state, fp16
__device__ __align__(16) __half g_Yh  [(size_t)NNODES*512]; // [yl(256,+b1) | yr(256)] fp16
__device__ __align__(16) float2 g_part[(size_t)NPAIR*384*8]; // (pm,ps) per (pair,row,ngroup)

// ---------------- mma / barrier helpers ----------------
__device__ __forceinline__ void ldsm_x4(unsigned &r0,unsigned &r1,unsigned &r2,unsigned &r3, unsigned a){
  asm volatile("ldmatrix.sync.aligned.m8n8.x4.shared.b16 {%0,%1,%2,%3},[%4];"
    :"=r"(r0),"=r"(r1),"=r"(r2),"=r"(r3):"r"(a));
}
__device__ __forceinline__ void ldsm_x2(unsigned &r0,unsigned &r1, unsigned a){
  asm volatile("ldmatrix.sync.aligned.m8n8.x2.shared.b16 {%0,%1},[%2];"
    :"=r"(r0),"=r"(r1):"r"(a));
}
__device__ __forceinline__ void mma16816(float c[4], const unsigned a[4], const unsigned b[2]){
  asm volatile("mma.sync.aligned.m16n8k16.row.col.f32.f16.f16.f32 "
    "{%0,%1,%2,%3},{%4,%5,%6,%7},{%8,%9},{%0,%1,%2,%3};"
    :"+f"(c[0]),"+f"(c[1]),"+f"(c[2]),"+f"(c[3])
    :"r"(a[0]),"r"(a[1]),"r"(a[2]),"r"(a[3]),"r"(b[0]),"r"(b[1]));
}
__device__ __forceinline__ void cp16(unsigned dst, const void* src){
  asm volatile("cp.async.cg.shared.global [%0], [%1], 16;" :: "r"(dst), "l"(src));
}
#define CP_COMMIT() asm volatile("cp.async.commit_group;" ::: "memory")
#define CP_WAIT0()  asm volatile("cp.async.wait_group 0;" ::: "memory")
#define BAR_SYNC(id, n)   asm volatile("bar.sync %0, %1;"   :: "r"(id), "r"(n) : "memory")
#define BAR_ARRIVE(id, n) asm volatile("bar.arrive %0, %1;" :: "r"(id), "r"(n) : "memory")

__device__ __forceinline__ float lky(float v){ return v > 0.f ? v : 0.01f*v; }
__device__ __forceinline__ float softplus_(float x){ return fmaxf(x,0.f) + log1pf(expf(-fabsf(x))); }

// ---------------- K0: weight conversion ----------------
__global__ void k_prep(const float* __restrict__ lin1_w, const float* __restrict__ lin2_w){
  int i = blockIdx.x*blockDim.x + threadIdx.x;   // 65536 threads
  if (i < H_*H_) g_W2h[i] = __float2half(lin2_w[i]);
  if (i < 512*C_){
    int o = i >> 7, c = i & 127;
    float v = (o < H_) ? lin1_w[o*(2*C_) + c] : lin1_w[(o-H_)*(2*C_) + C_ + c];
    g_Wcat[i] = __float2half(v);
  }
}

// ---------------- K1: s_bar -> g -> X (8 batches per block) ----------------
__global__ __launch_bounds__(256,1)
void k1_build(const float* __restrict__ state, const float* __restrict__ conv_w,
              const float* __restrict__ conv_b){
  extern __shared__ float sm1[];
  float* cw   = sm1;                 // 128 x 129
  float* sbar = cw + 128*129;        // 8 x 128
  float* gg   = sbar + 8*128;        // 8 x 128
  int tid = threadIdx.x;
  int b0  = blockIdx.x * 8;

  for (int i = tid; i < 128*128; i += 256){ int r = i>>7, c = i&127; cw[r*129+c] = conv_w[i]; }
  for (int idx = tid; idx < 8*128; idx += 256){
    int bb = idx >> 7, c = idx & 127;
    const float* sp = state + (size_t)(b0+bb)*ADIM*C_ + c;
    float s = 0.f;
    #pragma unroll
    for (int i = 0; i < ADIM; i++) s += sp[i*C_];
    sbar[idx] = s * (1.0f/14.0f);
  }
  __syncthreads();
  #pragma unroll
  for (int u = 0; u < 4; u++){
    int o = tid + u*256;
    int bb = o >> 7, h = o & 127;
    const float* sb = sbar + bb*128;
    const float* w  = cw + h*129;
    float acc = 0.f;
    #pragma unroll 8
    for (int c = 0; c < 128; c++) acc += sb[c]*w[c];
    gg[o] = fmaxf(acc + conv_b[h], 0.f);
  }
  __syncthreads();
  for (int idx = tid; idx < 8*ADIM*C_; idx += 256){
    int bb = idx / (ADIM*C_); int rem = idx - bb*(ADIM*C_);
    int c  = rem & 127;
    size_t node = (size_t)(b0+bb)*ADIM + (rem >> 7);
    g_Xh[node*C_ + c] = __float2half(gg[bb*128 + c] + state[node*C_ + c]);
  }
}

// ---------------- K2: Y = X @ Wcat^T, fp16 out, b1 folded ----------------
__global__ __launch_bounds__(256,1)
void k2_ygemm(const float* __restrict__ lin1_b){
  extern __shared__ __half sm2[];
  __half* As = sm2;             // 128 x 136
  __half* Bs = As + 128*136;    // 128 x 136
  int tid = threadIdx.x;
  int m0 = blockIdx.x * 128, n0 = blockIdx.y * 128;

  for (int idx = tid; idx < 128*16; idx += 256){
    int r = idx >> 4, c = idx & 15;
    *(uint4*)&As[r*136 + c*8] = *(const uint4*)&g_Xh [(size_t)(m0+r)*C_ + c*8];
    *(uint4*)&Bs[r*136 + c*8] = *(const uint4*)&g_Wcat[(size_t)(n0+r)*C_ + c*8];
  }
  __syncthreads();

  int lane = tid & 31, warp = tid >> 5, wm = warp >> 2, wn = warp & 3;
  unsigned abase = (unsigned)__cvta_generic_to_shared(As);
  unsigned bbase = (unsigned)__cvta_generic_to_shared(Bs);
  float acc[4][4][4];
  #pragma unroll
  for (int i=0;i<4;i++) for (int j=0;j<4;j++) for (int q=0;q<4;q++) acc[i][j][q]=0.f;

  int rA = (lane & 7) + ((lane >> 3) & 1) * 8;
  int cA = (lane >> 4) * 8;
  int l16 = lane & 15;
  int rB = l16 & 7;
  int cB = (l16 >> 3) * 8;

  #pragma unroll
  for (int kk = 0; kk < 8; kk++){
    int k0 = kk*16;
    unsigned a[4][4], b[4][2];
    #pragma unroll
    for (int mi = 0; mi < 4; mi++){
      int row = wm*64 + mi*16 + rA;
      ldsm_x4(a[mi][0],a[mi][1],a[mi][2],a[mi][3], abase + (row*136 + k0 + cA)*2);
    }
    #pragma unroll
    for (int ni = 0; ni < 4; ni++){
      int row = wn*32 + ni*8 + rB;
      ldsm_x2(b[ni][0],b[ni][1], bbase + (row*136 + k0 + cB)*2);
    }
    #pragma unroll
    for (int mi = 0; mi < 4; mi++)
      #pragma unroll
      for (int ni = 0; ni < 4; ni++)
        mma16816(acc[mi][ni], a[mi], b[ni]);
  }
  bool leftblk = (n0 < 256);
  #pragma unroll
  for (int ni = 0; ni < 4; ni++){
    int col = n0 + wn*32 + ni*8 + ((lane & 3) << 1);
    float a0 = leftblk ? __ldg(&lin1_b[col])   : 0.f;
    float a1 = leftblk ? __ldg(&lin1_b[col+1]) : 0.f;
    #pragma unroll
    for (int mi = 0; mi < 4; mi++){
      int row = m0 + wm*64 + mi*16 + (lane >> 2);
      *(__half2*)&g_Yh[(size_t)row*512 + col] =
        __floats2half2_rn(acc[mi][ni][0] + a0, acc[mi][ni][1] + a1);
      *(__half2*)&g_Yh[(size_t)(row+8)*512 + col] =
        __floats2half2_rn(acc[mi][ni][2] + a0, acc[mi][ni][3] + a1);
    }
  }
}

// ---------------- K3: warp-specialized, named-barrier pipelined GEMM ----------------
// 384 threads: warps 0-7 = GEMM (warp tile m64 x n32, 1m x 8n, chunk M=64),
// warps 8-11 = builders (H1 double-buffered) + Ys prefetch.
// Named barriers: ready0=1, ready1=2 (builders arrive, GEMM syncs);
//                 free0=3,  free1=4  (GEMM arrives, builders sync). Count=384.
__global__ __launch_bounds__(384,1)
void k3_main(const float* __restrict__ lin2_b,
             const float* __restrict__ mu_w, const float* __restrict__ sig_w){
  extern __shared__ __half sm3[];
  __half* Ys  = sm3;                 // 2 x 14 x 512 = 14336 halves (one pair)
  __half* W2s = Ys + 14336;          // 256 x 264 = 67584
  __half* H1a = W2s + 67584;         // 64 x 264
  __half* H1b = H1a + 16896;         // 64 x 264
  // total (14336 + 67584 + 2*16896)*2 = 231424 B

  int tid  = threadIdx.x;
  int lane = tid & 31, warp = tid >> 5;          // 12 warps
  bool isg = (warp < 8);
  int warp_n = warp & 7;

  // one-time: W2 into smem (stride 264)
  for (int idx = tid; idx < 256*32; idx += 384){
    int r = idx >> 5, c = idx & 31;
    *(uint4*)&W2s[r*264 + c*8] = ((const uint4*)g_W2h)[r*32 + c];
  }
  // per-thread head constants (GEMM warps)
  __half2 b2c[4], muc[4], sgc[4];
  if (isg){
    #pragma unroll
    for (int ni = 0; ni < 4; ni++){
      int col = warp_n*32 + ni*8 + ((lane & 3) << 1);
      b2c[ni] = __floats2half2_rn(__ldg(&lin2_b[col]), __ldg(&lin2_b[col+1]));
      muc[ni] = __floats2half2_rn(__ldg(&mu_w[col]),   __ldg(&mu_w[col+1]));
      sgc[ni] = __floats2half2_rn(__ldg(&sig_w[col]),  __ldg(&sig_w[col+1]));
    }
  }

  unsigned h1bs[2] = { (unsigned)__cvta_generic_to_shared(H1a),
                       (unsigned)__cvta_generic_to_shared(H1b) };
  unsigned ysb = (unsigned)__cvta_generic_to_shared(Ys);
  unsigned w2b = (unsigned)__cvta_generic_to_shared(W2s);
  int rA = (lane & 7) + ((lane >> 3) & 1) * 8;
  int cA = (lane >> 4) * 8;
  int l16 = lane & 15;
  int rBo = l16 & 7;
  int cB  = (l16 >> 3) * 8;

  const __half2 zero2 = __float2half2_rn(0.f);
  const __half2 s01   = __float2half2_rn(0.01f);

  int pstep = gridDim.x;
  int bt = tid & 127;   // builder-local index

  // initial Ys prefetch (builders only)
  if (!isg && blockIdx.x < NPAIR){
    const __half* src = g_Yh + (size_t)(blockIdx.x*2)*ADIM*512;
    for (int g = bt; g < 1792; g += 128) cp16(ysb + g*16, src + g*8);
    CP_COMMIT();
  }
  __syncthreads();   // W2s visible to all

  if (isg){
    // ================= GEMM role =================
    for (int pair = blockIdx.x; pair < NPAIR; pair += pstep){
      #pragma unroll 1
      for (int t = 0; t < 6; t++){
        int buf = t & 1;
        BAR_SYNC(1 + buf, 384);              // H1[buf] ready
        unsigned h1b = h1bs[buf];

        float acc[4][4][4];
        #pragma unroll
        for (int i=0;i<4;i++) for (int j=0;j<4;j++) for (int q=0;q<4;q++) acc[i][j][q]=0.f;

        unsigned a[2][4][4], bf[2][4][2];
        // prologue: fragments for kk=0
        #pragma unroll
        for (int mi = 0; mi < 4; mi++){
          int row = mi*16 + rA;
          ldsm_x4(a[0][mi][0],a[0][mi][1],a[0][mi][2],a[0][mi][3], h1b + (row*264 + cA)*2);
        }
        #pragma unroll
        for (int ni = 0; ni < 4; ni++){
          int row = warp_n*32 + ni*8 + rBo;
          ldsm_x2(bf[0][ni][0],bf[0][ni][1], w2b + (row*264 + cB)*2);
        }
        #pragma unroll
        for (int kk = 0; kk < 16; kk++){
          int cb = kk & 1, nb = cb ^ 1;
          if (kk < 15){
            int k1 = (kk+1)*16;
            #pragma unroll
            for (int mi = 0; mi < 4; mi++){
              int row = mi*16 + rA;
              ldsm_x4(a[nb][mi][0],a[nb][mi][1],a[nb][mi][2],a[nb][mi][3],
                      h1b + (row*264 + k1 + cA)*2);
            }
            #pragma unroll
            for (int ni = 0; ni < 4; ni++){
              int row = warp_n*32 + ni*8 + rBo;
              ldsm_x2(bf[nb][ni][0],bf[nb][ni][1], w2b + (row*264 + k1 + cB)*2);
            }
          }
          #pragma unroll
          for (int mi = 0; mi < 4; mi++)
            #pragma unroll
            for (int ni = 0; ni < 4; ni++)
              mma16816(acc[mi][ni], a[cb][mi], bf[cb][ni]);
        }
        BAR_ARRIVE(3 + buf, 384);            // H1[buf] free (epilogue doesn't read it)

        // ---- epilogue: +b2, leaky, mu/sig dots, shfl-reduce, STG partials ----
        float2* pbase = g_part + ((size_t)pair*384 + t*64)*8 + warp_n;
        #pragma unroll
        for (int mi = 0; mi < 4; mi++){
          float pm0=0.f, ps0=0.f, pm1=0.f, ps1=0.f;
          #pragma unroll
          for (int ni = 0; ni < 4; ni++){
            float2 bb = __half22float2(b2c[ni]);
            float2 mm = __half22float2(muc[ni]);
            float2 ss = __half22float2(sgc[ni]);
            float v0 = lky(acc[mi][ni][0] + bb.x);
            float v1 = lky(acc[mi][ni][1] + bb.y);
            float v2 = lky(acc[mi][ni][2] + bb.x);
            float v3 = lky(acc[mi][ni][3] + bb.y);
            pm0 += v0*mm.x + v1*mm.y;
            ps0 += v0*ss.x + v1*ss.y;
            pm1 += v2*mm.x + v3*mm.y;
            ps1 += v2*ss.x + v3*ss.y;
          }
          pm0 += __shfl_xor_sync(0xffffffffu, pm0, 1); pm0 += __shfl_xor_sync(0xffffffffu, pm0, 2);
          ps0 += __shfl_xor_sync(0xffffffffu, ps0, 1); ps0 += __shfl_xor_sync(0xffffffffu, ps0, 2);
          pm1 += __shfl_xor_sync(0xffffffffu, pm1, 1); pm1 += __shfl_xor_sync(0xffffffffu, pm1, 2);
          ps1 += __shfl_xor_sync(0xffffffffu, ps1, 1); ps1 += __shfl_xor_sync(0xffffffffu, ps1, 2);
          if ((lane & 3) == 0){
            int row = mi*16 + (lane >> 2);
            pbase[(size_t)row*8]     = make_float2(pm0, ps0);
            pbase[(size_t)(row+8)*8] = make_float2(pm1, ps1);
          }
        }
      }
    }
  } else {
    // ================= builder role =================
    int gc = 0;
    for (int pair = blockIdx.x; pair < NPAIR; pair += pstep){
      CP_WAIT0();                          // Ys for this pair landed
      #pragma unroll 1
      for (int t = 0; t < 6; t++){
        int buf = t & 1;
        if (gc >= 2) BAR_SYNC(3 + buf, 384);   // wait GEMM done with H1[buf]
        __half* H1d = buf ? H1b : H1a;
        #pragma unroll
        for (int it = 0; it < 16; it++){
          int idx = bt + it*128;           // 64*32 entries
          int m  = idx >> 5;
          int c8 = idx & 31;
          int rg = t*64 + m;               // 0..383
          int bsel = (rg >= 192) ? 1 : 0;
          int e = rg - 192*bsel;
          uint4 val;
          if (e < E_){
            int ii = e/13; int r = e - ii*13; int jj = r + (r >= ii ? 1 : 0);
            uint4 ul = *(const uint4*)&Ys[(bsel*ADIM + ii)*512 + c8*8];
            uint4 ur = *(const uint4*)&Ys[(bsel*ADIM + jj)*512 + 256 + c8*8];
            const __half2* l2 = (const __half2*)&ul;
            const __half2* r2 = (const __half2*)&ur;
            __half2 o[4];
            #pragma unroll
            for (int q = 0; q < 4; q++){
              __half2 s = __hadd2(l2[q], r2[q]);
              o[q] = __hadd2(__hmax2(s, zero2), __hmul2(s01, __hmin2(s, zero2)));
            }
            val = *(uint4*)o;
          } else {
            val = make_uint4(0u,0u,0u,0u);
          }
          *(uint4*)&H1d[m*264 + c8*8] = val;
        }
        BAR_ARRIVE(1 + buf, 384);          // H1[buf] ready
        gc++;
      }
      // Ys dead: prefetch next pair
      int pn = pair + pstep;
      if (pn < NPAIR){
        const __half* src = g_Yh + (size_t)(pn*2)*ADIM*512;
        for (int g = bt; g < 1792; g += 128) cp16(ysb + g*16, src + g*8);
      }
      CP_COMMIT();
    }
  }
}

// ---------------- K4: heads + log-prob from partials ----------------
__global__ __launch_bounds__(192,1)
void k4_heads(const float* __restrict__ mu_b, const float* __restrict__ sig_b,
              const float* __restrict__ noise, float* __restrict__ out){
  __shared__ float wsum[6];
  int b = blockIdx.x;                 // 0..2047
  int tid = threadIdx.x;              // 0..191
  int pair = b >> 1, half = b & 1;
  const float2* src = g_part + ((size_t)pair*384 + half*192 + tid)*8;
  float mp = mu_b[0], sp = sig_b[0];
  #pragma unroll
  for (int q = 0; q < 8; q++){ float2 v = src[q]; mp += v.x; sp += v.y; }
  float c = 0.f;
  if (tid < E_){
    float mu = softplus_(mp);
    float sd = softplus_(sp);
    float nz = noise[(size_t)b*E_ + tid];
    out[(size_t)b*E_ + tid] = mu + sd*nz;
    c = -0.5f*nz*nz - logf(sd);
  }
  c += __shfl_xor_sync(0xffffffffu, c, 1);
  c += __shfl_xor_sync(0xffffffffu, c, 2);
  c += __shfl_xor_sync(0xffffffffu, c, 4);
  c += __shfl_xor_sync(0xffffffffu, c, 8);
  c += __shfl_xor_sync(0xffffffffu, c, 16);
  if ((tid & 31) == 0) wsum[tid >> 5] = c;
  __syncthreads();
  if (tid == 0){
    float s = wsum[0] + wsum[1] + wsum[2] + wsum[3] + wsum[4] + wsum[5];
    out[(size_t)NROWS + b] = s - (float)E_ * 0.91893853320467274f;
  }
}

// ---------------- host launcher ----------------
extern "C" void kernel_launch(void* const* d_in, const int* in_sizes, int n_in,
                              void* d_out, int out_size){
  const float* state  = (const float*)d_in[0];
  const float* conv_w = (const float*)d_in[1];
  const float* conv_b = (const float*)d_in[2];
  const float* lin1_w = (const float*)d_in[3];
  const float* lin1_b = (const float*)d_in[4];
  const float* lin2_w = (const float*)d_in[5];
  const float* lin2_b = (const float*)d_in[6];
  const float* mu_w   = (const float*)d_in[7];
  const float* mu_b   = (const float*)d_in[8];
  const float* sig_w  = (const float*)d_in[9];
  const float* sig_b  = (const float*)d_in[10];
  const float* noise  = (const float*)d_in[11];
  float* out = (float*)d_out;

  const int SM1 = (128*129 + 8*128 + 8*128) * 4;           // 74240
  const int SM2 = 2 * 128*136 * 2;                         // 69632
  const int SM3 = (14336 + 256*264 + 2*64*264) * 2;        // 231424

  cudaFuncSetAttribute(k1_build, cudaFuncAttributeMaxDynamicSharedMemorySize, SM1);
  cudaFuncSetAttribute(k2_ygemm, cudaFuncAttributeMaxDynamicSharedMemorySize, SM2);
  cudaFuncSetAttribute(k3_main,  cudaFuncAttributeMaxDynamicSharedMemorySize, SM3);

  k_prep<<<256, 256>>>(lin1_w, lin2_w);
  k1_build<<<256, 256, SM1>>>(state, conv_w, conv_b);
  k2_ygemm<<<dim3(224, 4), 256, SM2>>>(lin1_b);
  k3_main<<<152, 384, SM3>>>(lin2_b, mu_w, sig_w);
  k4_heads<<<B_, 192>>>(mu_b, sig_b, noise, out);
}